// round 1
// baseline (speedup 1.0000x reference)
#include <cuda_runtime.h>
#include <cstdint>

// Problem constants
#define T_LEN   2048
#define BATCH   2
#define D_MODEL 512
#define S_WIN   32
#define M_ROWS  4096           // T*B
#define NCH     1024           // B*D channels

// ---------------- scratch (no allocation allowed) ----------------
__device__ float g_q[M_ROWS * D_MODEL];
__device__ float g_k[M_ROWS * D_MODEL];
__device__ float g_v[M_ROWS * D_MODEL];
__device__ float g_y[M_ROWS * D_MODEL];
__device__ float g_csn[M_ROWS * D_MODEL];
__device__ float g_csd[M_ROWS * D_MODEL];
__device__ float g_colmax_part[16 * T_LEN];
__device__ float g_colmax[T_LEN];
__device__ float g_mlp[16 * D_MODEL];
__device__ float g_ml[D_MODEL];

#define NCHUNK 64
#define CHLEN  32              // NCHUNK*CHLEN == T_LEN
__device__ float g_pnum[NCHUNK * NCH];
__device__ float g_pden[NCHUNK * NCH];

// ---------------- tf32 mma helpers ----------------
__device__ __forceinline__ float to_tf32(float x) {
    uint32_t u;
    asm("cvt.rna.tf32.f32 %0, %1;" : "=r"(u) : "f"(x));
    return __uint_as_float(u);
}

__device__ __forceinline__ void mma8(float c[4], const uint32_t a[4], const uint32_t b[2]) {
    asm volatile(
        "mma.sync.aligned.m16n8k8.row.col.f32.tf32.tf32.f32 "
        "{%0,%1,%2,%3}, {%4,%5,%6,%7}, {%8,%9}, {%0,%1,%2,%3};\n"
        : "+f"(c[0]), "+f"(c[1]), "+f"(c[2]), "+f"(c[3])
        : "r"(a[0]), "r"(a[1]), "r"(a[2]), "r"(a[3]),
          "r"(b[0]), "r"(b[1]));
}

// ---------------- GEMM: C[M,512] = A[M,512] @ W[512,512]^T + bias ----------------
// BM=128, BN=64, BK=32; 256 threads (8 warps: 4 x-m, 2 x-n), warp tile 32x32.
#define BM 128
#define BN 64
#define BK 32

__global__ __launch_bounds__(256) void gemm_tf32(
    const float* __restrict__ A, const float* __restrict__ W,
    const float* __restrict__ bias, float* __restrict__ C)
{
    __shared__ float As[BM][BK + 4];
    __shared__ float Ws[BN][BK + 4];

    const int tid  = threadIdx.x;
    const int lane = tid & 31;
    const int w    = tid >> 5;
    const int wm   = w & 3;   // 0..3
    const int wn   = w >> 2;  // 0..1
    const int bx   = blockIdx.x;  // m block (32)
    const int by   = blockIdx.y;  // n block (8)

    float acc[2][4][4];
#pragma unroll
    for (int mt = 0; mt < 2; mt++)
#pragma unroll
        for (int nt = 0; nt < 4; nt++)
#pragma unroll
            for (int i = 0; i < 4; i++) acc[mt][nt][i] = 0.0f;

    const int r_fr = lane >> 2;      // 0..7
    const int c_fr = lane & 3;       // 0..3

    for (int kt = 0; kt < 512; kt += BK) {
        // load A tile: 128x32 floats, float4 per slot
#pragma unroll
        for (int i = 0; i < 4; i++) {
            int slot = tid + i * 256;
            int r = slot >> 3, c4 = (slot & 7) << 2;
            float4 v4 = *reinterpret_cast<const float4*>(&A[(size_t)(bx * BM + r) * 512 + kt + c4]);
            As[r][c4 + 0] = to_tf32(v4.x);
            As[r][c4 + 1] = to_tf32(v4.y);
            As[r][c4 + 2] = to_tf32(v4.z);
            As[r][c4 + 3] = to_tf32(v4.w);
        }
        // load W tile: 64x32
#pragma unroll
        for (int i = 0; i < 2; i++) {
            int slot = tid + i * 256;
            int r = slot >> 3, c4 = (slot & 7) << 2;
            float4 v4 = *reinterpret_cast<const float4*>(&W[(size_t)(by * BN + r) * 512 + kt + c4]);
            Ws[r][c4 + 0] = to_tf32(v4.x);
            Ws[r][c4 + 1] = to_tf32(v4.y);
            Ws[r][c4 + 2] = to_tf32(v4.z);
            Ws[r][c4 + 3] = to_tf32(v4.w);
        }
        __syncthreads();

#pragma unroll
        for (int ks = 0; ks < 4; ks++) {
            uint32_t a[2][4], b[4][2];
            const int kk = ks * 8;
#pragma unroll
            for (int mt = 0; mt < 2; mt++) {
                int m0 = wm * 32 + mt * 16;
                a[mt][0] = __float_as_uint(As[m0 + r_fr    ][kk + c_fr    ]);
                a[mt][1] = __float_as_uint(As[m0 + r_fr + 8][kk + c_fr    ]);
                a[mt][2] = __float_as_uint(As[m0 + r_fr    ][kk + c_fr + 4]);
                a[mt][3] = __float_as_uint(As[m0 + r_fr + 8][kk + c_fr + 4]);
            }
#pragma unroll
            for (int nt = 0; nt < 4; nt++) {
                int n0 = wn * 32 + nt * 8 + r_fr;
                b[nt][0] = __float_as_uint(Ws[n0][kk + c_fr    ]);
                b[nt][1] = __float_as_uint(Ws[n0][kk + c_fr + 4]);
            }
#pragma unroll
            for (int mt = 0; mt < 2; mt++)
#pragma unroll
                for (int nt = 0; nt < 4; nt++)
                    mma8(acc[mt][nt], a[mt], b[nt]);
        }
        __syncthreads();
    }

    // epilogue
    const int c2 = (lane & 3) * 2;
#pragma unroll
    for (int mt = 0; mt < 2; mt++) {
#pragma unroll
        for (int nt = 0; nt < 4; nt++) {
            int row = bx * BM + wm * 32 + mt * 16 + r_fr;
            int col = by * BN + wn * 32 + nt * 8 + c2;
            float b0 = bias[col], b1 = bias[col + 1];
            C[(size_t)row * 512 + col    ] = acc[mt][nt][0] + b0;
            C[(size_t)row * 512 + col + 1] = acc[mt][nt][1] + b1;
            C[(size_t)(row + 8) * 512 + col    ] = acc[mt][nt][2] + b0;
            C[(size_t)(row + 8) * 512 + col + 1] = acc[mt][nt][3] + b1;
        }
    }
}

// ---------------- pos_bias column max (two phase) ----------------
__global__ void colmax1_kernel(const float* __restrict__ pb) {
    int col = blockIdx.x * 256 + threadIdx.x;   // gridDim.x = 8
    int r0  = blockIdx.y * 128;                 // gridDim.y = 16
    float m = -1e30f;
#pragma unroll 4
    for (int i = 0; i < 128; i++)
        m = fmaxf(m, pb[(size_t)(r0 + i) * T_LEN + col]);
    g_colmax_part[blockIdx.y * T_LEN + col] = m;
}

__global__ void colmax2_kernel() {
    int col = blockIdx.x * 256 + threadIdx.x;
    float m = -1e30f;
#pragma unroll
    for (int i = 0; i < 16; i++)
        m = fmaxf(m, g_colmax_part[i * T_LEN + col]);
    g_colmax[col] = m;
}

// ---------------- max_logit (batch 0 only, matches reference [0]) ----------------
__global__ void mlpart_kernel() {
    int d  = threadIdx.x;           // 512
    int t0 = blockIdx.x * 128;      // 16 blocks
    float m = -1e30f;
    for (int i = 0; i < 128; i++) {
        int t = t0 + i;
        float kv = g_k[(size_t)t * NCH + d];   // batch 0 -> channel d
        float cm = g_colmax[t];
        m = fmaxf(m, fmaxf(kv, kv + cm));
    }
    g_mlp[blockIdx.x * D_MODEL + d] = m;
}

__global__ void mlfinal_kernel() {
    int d = threadIdx.x;
    float m = -1e30f;
#pragma unroll
    for (int i = 0; i < 16; i++)
        m = fmaxf(m, g_mlp[i * D_MODEL + d]);
    g_ml[d] = m;
}

// ---------------- chunked scan of ek, ek*v over T ----------------
__global__ void scanA_kernel() {
    int ch = blockIdx.x * 256 + threadIdx.x;  // gridDim.x = 4
    int t0 = blockIdx.y * CHLEN;              // gridDim.y = NCHUNK
    float ml = g_ml[ch & (D_MODEL - 1)];
    float sn = 0.f, sd = 0.f;
#pragma unroll 4
    for (int i = 0; i < CHLEN; i++) {
        int t = t0 + i;
        float e = __expf(g_k[(size_t)t * NCH + ch] - ml);
        sd += e;
        sn += e * g_v[(size_t)t * NCH + ch];
    }
    g_pden[blockIdx.y * NCH + ch] = sd;
    g_pnum[blockIdx.y * NCH + ch] = sn;
}

__global__ void scanB_kernel() {
    int ch = threadIdx.x;  // 1024
    float rd = 0.f, rn = 0.f;
    for (int c = 0; c < NCHUNK; c++) {
        int i = c * NCH + ch;
        float td = g_pden[i], tn = g_pnum[i];
        g_pden[i] = rd; g_pnum[i] = rn;   // exclusive offsets
        rd += td; rn += tn;
    }
}

__global__ void scanC_kernel() {
    int ch = blockIdx.x * 256 + threadIdx.x;
    int t0 = blockIdx.y * CHLEN;
    float ml = g_ml[ch & (D_MODEL - 1)];
    float rn = g_pnum[blockIdx.y * NCH + ch];
    float rd = g_pden[blockIdx.y * NCH + ch];
#pragma unroll 4
    for (int i = 0; i < CHLEN; i++) {
        int t = t0 + i;
        float e = __expf(g_k[(size_t)t * NCH + ch] - ml);
        rd += e;
        rn += e * g_v[(size_t)t * NCH + ch];
        g_csd[(size_t)t * NCH + ch] = rd;
        g_csn[(size_t)t * NCH + ch] = rn;
    }
}

// ---------------- AFT local window + gating ----------------
// 32 t-values x 32 channels per block; warp = 1 t-row x 32 ch (coalesced).
__global__ __launch_bounds__(256) void aft_kernel(const float* __restrict__ pb) {
    const int lane = threadIdx.x & 31;
    const int w    = threadIdx.x >> 5;
    const int t0   = blockIdx.x * 32;       // 64 blocks
    const int ch   = blockIdx.y * 32 + lane; // 32 blocks
    const float ml = g_ml[ch & (D_MODEL - 1)];

#pragma unroll
    for (int i = 0; i < 4; i++) {
        int t = t0 + w + 8 * i;
        float num = 0.f, den = 0.f;
        if (t >= S_WIN) {
            num = g_csn[(size_t)(t - S_WIN) * NCH + ch];
            den = g_csd[(size_t)(t - S_WIN) * NCH + ch];
        }
        const float* pbrow = pb + (size_t)t * T_LEN;
        int jstart = (t >= 31) ? 0 : (31 - t);
        for (int j = jstart; j < 32; j++) {
            int idx = t - 31 + j;
            float e = __expf(g_k[(size_t)idx * NCH + ch] + pbrow[idx] - ml);
            num += e * g_v[(size_t)idx * NCH + ch];
            den += e;
        }
        float qv  = g_q[(size_t)t * NCH + ch];
        float sig = 1.0f / (1.0f + __expf(-qv));
        g_y[(size_t)t * NCH + ch] = sig * num / den;
    }
}

// ---------------- launch ----------------
extern "C" void kernel_launch(void* const* d_in, const int* in_sizes, int n_in,
                              void* d_out, int out_size) {
    const float* query = (const float*)d_in[0];
    const float* key   = (const float*)d_in[1];
    const float* value = (const float*)d_in[2];
    const float* Wq    = (const float*)d_in[3];
    const float* bq    = (const float*)d_in[4];
    const float* Wk    = (const float*)d_in[5];
    const float* bk    = (const float*)d_in[6];
    const float* Wv    = (const float*)d_in[7];
    const float* bv    = (const float*)d_in[8];
    const float* pb    = (const float*)d_in[9];
    const float* Wo    = (const float*)d_in[10];
    const float* bo    = (const float*)d_in[11];
    float* out = (float*)d_out;

    float *pq, *pk, *pv, *py;
    cudaGetSymbolAddress((void**)&pq, g_q);
    cudaGetSymbolAddress((void**)&pk, g_k);
    cudaGetSymbolAddress((void**)&pv, g_v);
    cudaGetSymbolAddress((void**)&py, g_y);

    dim3 ggrid(M_ROWS / BM, 512 / BN);   // (32, 8)

    gemm_tf32<<<ggrid, 256>>>(query, Wq, bq, pq);
    gemm_tf32<<<ggrid, 256>>>(key,   Wk, bk, pk);
    gemm_tf32<<<ggrid, 256>>>(value, Wv, bv, pv);

    colmax1_kernel<<<dim3(8, 16), 256>>>(pb);
    colmax2_kernel<<<8, 256>>>();
    mlpart_kernel<<<16, 512>>>();
    mlfinal_kernel<<<1, 512>>>();

    scanA_kernel<<<dim3(4, NCHUNK), 256>>>();
    scanB_kernel<<<1, 1024>>>();
    scanC_kernel<<<dim3(4, NCHUNK), 256>>>();

    aft_kernel<<<dim3(64, 32), 256>>>(pb);

    gemm_tf32<<<ggrid, 256>>>(py, Wo, bo, out);
}

// round 3
// speedup vs baseline: 1.6112x; 1.6112x over previous
#include <cuda_runtime.h>
#include <cstdint>

// ---------------- problem constants ----------------
#define T_LEN   2048
#define BATCH   2
#define D_MODEL 512
#define S_WIN   32
#define M_ROWS  4096           // T*B
#define NCH     1024           // B*D channels

// ---------------- scratch (no allocation allowed) ----------------
__device__ float g_q[M_ROWS * D_MODEL];
__device__ float g_k[M_ROWS * D_MODEL];
__device__ float g_v[M_ROWS * D_MODEL];
__device__ float g_y[M_ROWS * D_MODEL];
__device__ float g_csn[M_ROWS * D_MODEL];
__device__ float g_csd[M_ROWS * D_MODEL];
__device__ float g_ek[M_ROWS * D_MODEL];
__device__ float g_colmax_part[128 * T_LEN];
__device__ float g_colmax[T_LEN];
__device__ float g_mlp[64 * D_MODEL];
__device__ float g_ml[D_MODEL];
__device__ float g_epb[T_LEN * S_WIN];

#define NCHUNK 64
#define CHLEN  32              // NCHUNK*CHLEN == T_LEN
__device__ float g_pnum[NCHUNK * NCH];
__device__ float g_pden[NCHUNK * NCH];

// ---------------- helpers ----------------
__device__ __forceinline__ uint32_t smem_to_u32(const void* p) {
    uint32_t a;
    asm("{ .reg .u64 t; cvta.to.shared.u64 t, %1; cvt.u32.u64 %0, t; }" : "=r"(a) : "l"(p));
    return a;
}
__device__ __forceinline__ uint32_t to_tf32_bits(float x) {
    uint32_t u;
    asm("cvt.rna.tf32.f32 %0, %1;" : "=r"(u) : "f"(x));
    return u;
}
__device__ __forceinline__ void mma8(float c[4], const uint32_t a[4], const uint32_t b[2]) {
    asm volatile(
        "mma.sync.aligned.m16n8k8.row.col.f32.tf32.tf32.f32 "
        "{%0,%1,%2,%3}, {%4,%5,%6,%7}, {%8,%9}, {%0,%1,%2,%3};\n"
        : "+f"(c[0]), "+f"(c[1]), "+f"(c[2]), "+f"(c[3])
        : "r"(a[0]), "r"(a[1]), "r"(a[2]), "r"(a[3]),
          "r"(b[0]), "r"(b[1]));
}
__device__ __forceinline__ void cp16(uint32_t dst, const void* src) {
    asm volatile("cp.async.cg.shared.global [%0], [%1], 16;" :: "r"(dst), "l"(src));
}
__device__ __forceinline__ void cp_commit() {
    asm volatile("cp.async.commit_group;" ::: "memory");
}

// ---------------- pipelined tf32 GEMM: C[M,512] = A[M,512] @ W[512,512]^T + bias --------
// BM=128, BN=128, BK=32, 3-stage cp.async; 256 threads, 8 warps (2m x 4n), warp 64x32.
#define GBM 128
#define GBN 128
#define GBK 32
#define GSTG 3
#define NKT 16                    // 512/GBK
#define PADK 36                   // floats per smem row (144B, 16B-aligned, conflict-free)
#define A_STG (GBM * PADK)        // floats
#define B_STG (GBN * PADK)
#define STG_FLOATS (A_STG + B_STG)
#define GEMM_SMEM (GSTG * STG_FLOATS * 4)   // 110,592 B

__device__ __forceinline__ void ld_stage(uint32_t sb, const float* __restrict__ A,
                                         const float* __restrict__ W,
                                         int bm, int bn, int kt, int tid) {
    uint32_t base = sb + (uint32_t)((kt % GSTG) * STG_FLOATS * 4);
#pragma unroll
    for (int i = 0; i < 4; i++) {
        int chunk = tid + i * 256;             // 0..1023 : 128 rows x 8 chunks
        int row = chunk >> 3, c16 = chunk & 7;
        cp16(base + (uint32_t)(row * PADK + c16 * 4) * 4,
             &A[(size_t)(bm * GBM + row) * 512 + kt * GBK + c16 * 4]);
    }
    base += A_STG * 4;
#pragma unroll
    for (int i = 0; i < 4; i++) {
        int chunk = tid + i * 256;
        int row = chunk >> 3, c16 = chunk & 7;
        cp16(base + (uint32_t)(row * PADK + c16 * 4) * 4,
             &W[(size_t)(bn * GBN + row) * 512 + kt * GBK + c16 * 4]);
    }
    cp_commit();
}

__global__ void __launch_bounds__(256, 2) gemm_qkv(
    const float* __restrict__ A0, const float* __restrict__ A1, const float* __restrict__ A2,
    const float* __restrict__ W0, const float* __restrict__ W1, const float* __restrict__ W2,
    const float* __restrict__ B0, const float* __restrict__ B1, const float* __restrict__ B2,
    float* __restrict__ C0, float* __restrict__ C1, float* __restrict__ C2)
{
    extern __shared__ float smem[];
    const uint32_t sb = smem_to_u32(smem);
    const int tid  = threadIdx.x;
    const int lane = tid & 31;
    const int wid  = tid >> 5;
    const int wm   = wid & 1;        // 2 warps in m
    const int wn   = wid >> 1;       // 4 warps in n
    const int bm   = blockIdx.x, bn = blockIdx.y;
    const int z    = blockIdx.z;

    const float* A    = (z == 0) ? A0 : (z == 1) ? A1 : A2;
    const float* W    = (z == 0) ? W0 : (z == 1) ? W1 : W2;
    const float* bias = (z == 0) ? B0 : (z == 1) ? B1 : B2;
    float*       C    = (z == 0) ? C0 : (z == 1) ? C1 : C2;

    const int r_fr = lane >> 2;      // 0..7
    const int c_fr = lane & 3;       // 0..3

    float acc[4][4][4];
#pragma unroll
    for (int mt = 0; mt < 4; mt++)
#pragma unroll
        for (int nt = 0; nt < 4; nt++)
#pragma unroll
            for (int i = 0; i < 4; i++) acc[mt][nt][i] = 0.0f;

    // prologue: stages 0,1
    ld_stage(sb, A, W, bm, bn, 0, tid);
    ld_stage(sb, A, W, bm, bn, 1, tid);

#pragma unroll 1
    for (int kt = 0; kt < NKT; kt++) {
        if (kt < NKT - 2) asm volatile("cp.async.wait_group 1;" ::: "memory");
        else              asm volatile("cp.async.wait_group 0;" ::: "memory");
        __syncthreads();

        if (kt + 2 < NKT) ld_stage(sb, A, W, bm, bn, kt + 2, tid);

        const float* As = smem + (kt % GSTG) * STG_FLOATS;
        const float* Bs = As + A_STG;
#pragma unroll
        for (int ks = 0; ks < 4; ks++) {
            const int kk = ks * 8;
            uint32_t a[4][4], b[4][2];
#pragma unroll
            for (int mt = 0; mt < 4; mt++) {
                int m0 = wm * 64 + mt * 16 + r_fr;
                a[mt][0] = to_tf32_bits(As[(m0    ) * PADK + kk + c_fr    ]);
                a[mt][1] = to_tf32_bits(As[(m0 + 8) * PADK + kk + c_fr    ]);
                a[mt][2] = to_tf32_bits(As[(m0    ) * PADK + kk + c_fr + 4]);
                a[mt][3] = to_tf32_bits(As[(m0 + 8) * PADK + kk + c_fr + 4]);
            }
#pragma unroll
            for (int nt = 0; nt < 4; nt++) {
                int n0 = wn * 32 + nt * 8 + r_fr;
                b[nt][0] = to_tf32_bits(Bs[n0 * PADK + kk + c_fr    ]);
                b[nt][1] = to_tf32_bits(Bs[n0 * PADK + kk + c_fr + 4]);
            }
#pragma unroll
            for (int mt = 0; mt < 4; mt++)
#pragma unroll
                for (int nt = 0; nt < 4; nt++)
                    mma8(acc[mt][nt], a[mt], b[nt]);
        }
    }

    // epilogue: bias + float2 stores
    const int c2 = (lane & 3) * 2;
#pragma unroll
    for (int mt = 0; mt < 4; mt++) {
#pragma unroll
        for (int nt = 0; nt < 4; nt++) {
            int row = bm * GBM + wm * 64 + mt * 16 + r_fr;
            int col = bn * GBN + wn * 32 + nt * 8 + c2;
            float b0 = bias[col], b1 = bias[col + 1];
            *reinterpret_cast<float2*>(&C[(size_t)row * 512 + col]) =
                make_float2(acc[mt][nt][0] + b0, acc[mt][nt][1] + b1);
            *reinterpret_cast<float2*>(&C[(size_t)(row + 8) * 512 + col]) =
                make_float2(acc[mt][nt][2] + b0, acc[mt][nt][3] + b1);
        }
    }
}

// ---------------- pos_bias column max (two phase, vectorized) ----------------
__global__ void colmax1_kernel(const float* __restrict__ pb) {
    int c4 = (blockIdx.x * 256 + threadIdx.x) << 2;   // gridDim.x = 2
    int r0 = blockIdx.y << 4;                         // gridDim.y = 128 (16 rows each)
    float4 m = make_float4(-1e30f, -1e30f, -1e30f, -1e30f);
#pragma unroll
    for (int i = 0; i < 16; i++) {
        float4 v = *reinterpret_cast<const float4*>(&pb[(size_t)(r0 + i) * T_LEN + c4]);
        m.x = fmaxf(m.x, v.x); m.y = fmaxf(m.y, v.y);
        m.z = fmaxf(m.z, v.z); m.w = fmaxf(m.w, v.w);
    }
    *reinterpret_cast<float4*>(&g_colmax_part[blockIdx.y * T_LEN + c4]) = m;
}

__global__ void colmax2_kernel() {
    int c4 = (blockIdx.x * 256 + threadIdx.x) << 2;   // gridDim.x = 2
    float4 m = make_float4(-1e30f, -1e30f, -1e30f, -1e30f);
#pragma unroll 8
    for (int i = 0; i < 128; i++) {
        float4 v = *reinterpret_cast<float4*>(&g_colmax_part[i * T_LEN + c4]);
        m.x = fmaxf(m.x, v.x); m.y = fmaxf(m.y, v.y);
        m.z = fmaxf(m.z, v.z); m.w = fmaxf(m.w, v.w);
    }
    *reinterpret_cast<float4*>(&g_colmax[c4]) = m;
}

// ---------------- max_logit (batch 0 only, matches reference [0]) ----------------
__global__ void mlpart_kernel() {
    int d  = threadIdx.x;           // 512
    int t0 = blockIdx.x * 32;       // 64 blocks
    float m = -1e30f;
#pragma unroll 4
    for (int i = 0; i < 32; i++) {
        int t = t0 + i;
        float kv = g_k[(size_t)t * NCH + d];   // batch 0 -> channel d
        float cm = g_colmax[t];
        m = fmaxf(m, fmaxf(kv, kv + cm));
    }
    g_mlp[blockIdx.x * D_MODEL + d] = m;
}

__global__ void mlfinal_kernel() {
    int d = threadIdx.x;
    float m = -1e30f;
#pragma unroll
    for (int i = 0; i < 64; i++)
        m = fmaxf(m, g_mlp[i * D_MODEL + d]);
    g_ml[d] = m;
}

// ---------------- exp(pb) window table ----------------
__global__ void epb_kernel(const float* __restrict__ pb) {
    int id = blockIdx.x * 256 + threadIdx.x;   // grid 256 -> 65536
    int t = id >> 5, j = id & 31;
    int idx = t - (S_WIN - 1) + j;
    g_epb[id] = (idx >= 0) ? __expf(pb[(size_t)t * T_LEN + idx]) : 0.0f;
}

// ---------------- chunked scan of ek, ek*v over T ----------------
__global__ void scanA_kernel() {
    int ch = blockIdx.x * 256 + threadIdx.x;  // gridDim.x = 4
    int t0 = blockIdx.y * CHLEN;              // gridDim.y = NCHUNK
    float ml = g_ml[ch & (D_MODEL - 1)];
    float sn = 0.f, sd = 0.f;
#pragma unroll 4
    for (int i = 0; i < CHLEN; i++) {
        int t = t0 + i;
        float e = __expf(g_k[(size_t)t * NCH + ch] - ml);
        sd += e;
        sn += e * g_v[(size_t)t * NCH + ch];
    }
    g_pden[blockIdx.y * NCH + ch] = sd;
    g_pnum[blockIdx.y * NCH + ch] = sn;
}

__global__ void scanB_kernel() {
    int ch = blockIdx.x * 256 + threadIdx.x;  // grid 4 x 256 = 1024 channels
    float rd = 0.f, rn = 0.f;
    for (int c = 0; c < NCHUNK; c++) {
        int i = c * NCH + ch;
        float td = g_pden[i], tn = g_pnum[i];
        g_pden[i] = rd; g_pnum[i] = rn;   // exclusive offsets
        rd += td; rn += tn;
    }
}

__global__ void scanC_kernel() {
    int ch = blockIdx.x * 256 + threadIdx.x;
    int t0 = blockIdx.y * CHLEN;
    float ml = g_ml[ch & (D_MODEL - 1)];
    float rn = g_pnum[blockIdx.y * NCH + ch];
    float rd = g_pden[blockIdx.y * NCH + ch];
#pragma unroll 4
    for (int i = 0; i < CHLEN; i++) {
        int t = t0 + i;
        float e = __expf(g_k[(size_t)t * NCH + ch] - ml);
        g_ek[(size_t)t * NCH + ch] = e;
        rd += e;
        rn += e * g_v[(size_t)t * NCH + ch];
        g_csd[(size_t)t * NCH + ch] = rd;
        g_csn[(size_t)t * NCH + ch] = rn;
    }
}

// ---------------- AFT local window + gating (FMA-only inner loop) ----------------
// Block: 32 t-values x 64 channels (float2/thread). ek/v halo staged in smem.
__global__ __launch_bounds__(256) void aft_kernel() {
    __shared__ float2 s_ek[63 * 32];
    __shared__ float2 s_v [63 * 32];
    __shared__ float  s_epb[32 * 32];

    const int tid = threadIdx.x;
    const int w = tid >> 5, l = tid & 31;
    const int t0 = blockIdx.x << 5;                // 64 blocks
    const int chp = blockIdx.y * 32 + l;           // float2 channel index (0..511)

    const float2* ek2 = reinterpret_cast<const float2*>(g_ek);
    const float2* v2g = reinterpret_cast<const float2*>(g_v);

    for (int i = tid; i < 63 * 32; i += 256) {
        int r = i >> 5, cp = i & 31;
        int gr = t0 - 31 + r;
        float2 e = make_float2(0.f, 0.f), vv = make_float2(0.f, 0.f);
        if (gr >= 0) {
            size_t gi = (size_t)gr * 512 + blockIdx.y * 32 + cp;
            e  = ek2[gi];
            vv = v2g[gi];
        }
        s_ek[i] = e; s_v[i] = vv;
    }
    for (int i = tid; i < 1024; i += 256)
        s_epb[i] = g_epb[t0 * 32 + i];
    __syncthreads();

    const float2* csn2 = reinterpret_cast<const float2*>(g_csn);
    const float2* csd2 = reinterpret_cast<const float2*>(g_csd);
    const float2* q2g  = reinterpret_cast<const float2*>(g_q);
    float2* y2 = reinterpret_cast<float2*>(g_y);

#pragma unroll
    for (int ii = 0; ii < 4; ii++) {
        int tl = w + (ii << 3);        // 0..31
        int t  = t0 + tl;
        float nx = 0.f, ny = 0.f, dx = 0.f, dy = 0.f;
        if (t >= S_WIN) {
            float2 n0 = csn2[(size_t)(t - S_WIN) * 512 + chp];
            float2 d0 = csd2[(size_t)(t - S_WIN) * 512 + chp];
            nx = n0.x; ny = n0.y; dx = d0.x; dy = d0.y;
        }
#pragma unroll 8
        for (int j = 0; j < 32; j++) {
            float  ep = s_epb[(tl << 5) + j];          // warp-uniform broadcast
            float2 e2 = s_ek[((tl + j) << 5) + l];
            float2 vv = s_v [((tl + j) << 5) + l];
            float ex = e2.x * ep, ey = e2.y * ep;
            nx += ex * vv.x; ny += ey * vv.y;
            dx += ex;        dy += ey;
        }
        float2 q = q2g[(size_t)t * 512 + chp];
        float sx = 1.f / (1.f + __expf(-q.x));
        float sy = 1.f / (1.f + __expf(-q.y));
        y2[(size_t)t * 512 + chp] = make_float2(sx * nx / dx, sy * ny / dy);
    }
}

// ---------------- launch ----------------
extern "C" void kernel_launch(void* const* d_in, const int* in_sizes, int n_in,
                              void* d_out, int out_size) {
    const float* query = (const float*)d_in[0];
    const float* key   = (const float*)d_in[1];
    const float* value = (const float*)d_in[2];
    const float* Wq    = (const float*)d_in[3];
    const float* bq    = (const float*)d_in[4];
    const float* Wk    = (const float*)d_in[5];
    const float* bk    = (const float*)d_in[6];
    const float* Wv    = (const float*)d_in[7];
    const float* bv    = (const float*)d_in[8];
    const float* pb    = (const float*)d_in[9];
    const float* Wo    = (const float*)d_in[10];
    const float* bo    = (const float*)d_in[11];
    float* out = (float*)d_out;

    float *pq, *pk, *pv, *py;
    cudaGetSymbolAddress((void**)&pq, g_q);
    cudaGetSymbolAddress((void**)&pk, g_k);
    cudaGetSymbolAddress((void**)&pv, g_v);
    cudaGetSymbolAddress((void**)&py, g_y);

    cudaFuncSetAttribute(gemm_qkv, cudaFuncAttributeMaxDynamicSharedMemorySize, GEMM_SMEM);

    // epb / colmax do not depend on the GEMMs; launch first to overlap nothing is needed,
    // but order keeps the stream simple.
    epb_kernel<<<256, 256>>>(pb);
    colmax1_kernel<<<dim3(2, 128), 256>>>(pb);
    colmax2_kernel<<<2, 256>>>();

    dim3 ggrid3(M_ROWS / GBM, D_MODEL / GBN, 3);   // (32, 4, 3)
    gemm_qkv<<<ggrid3, 256, GEMM_SMEM>>>(query, key, value,
                                         Wq, Wk, Wv,
                                         bq, bk, bv,
                                         pq, pk, pv);

    mlpart_kernel<<<64, 512>>>();
    mlfinal_kernel<<<1, 512>>>();

    scanA_kernel<<<dim3(4, NCHUNK), 256>>>();
    scanB_kernel<<<4, 256>>>();
    scanC_kernel<<<dim3(4, NCHUNK), 256>>>();

    aft_kernel<<<dim3(64, 16), 256>>>();

    dim3 ggrid1(M_ROWS / GBM, D_MODEL / GBN, 1);
    gemm_qkv<<<ggrid1, 256, GEMM_SMEM>>>(py, py, py,
                                         Wo, Wo, Wo,
                                         bo, bo, bo,
                                         out, out, out);
}

// round 4
// speedup vs baseline: 1.6521x; 1.0254x over previous
#include <cuda_runtime.h>
#include <cstdint>

// ---------------- problem constants ----------------
#define T_LEN   2048
#define BATCH   2
#define D_MODEL 512
#define S_WIN   32
#define M_ROWS  4096           // T*B
#define NCH     1024           // B*D channels

// ---------------- scratch (no allocation allowed) ----------------
__device__ float g_q[M_ROWS * D_MODEL];
__device__ float g_k[M_ROWS * D_MODEL];
__device__ float g_v[M_ROWS * D_MODEL];
__device__ float g_y[M_ROWS * D_MODEL];
__device__ float g_csn[M_ROWS * D_MODEL];   // ALSO: rounded query before gemm
__device__ float g_csd[M_ROWS * D_MODEL];   // ALSO: rounded key   before gemm
__device__ float g_ek[M_ROWS * D_MODEL];    // ALSO: rounded value before gemm
__device__ float g_wr[3 * D_MODEL * D_MODEL];   // rounded Wq,Wk,Wv
__device__ float g_wor[D_MODEL * D_MODEL];      // rounded Wo
__device__ float g_colmax_part[128 * T_LEN];
__device__ float g_colmax[T_LEN];
__device__ unsigned int g_mlu[D_MODEL];
__device__ float g_epb[T_LEN * S_WIN];

#define NCHUNK 64
#define CHLEN  32              // NCHUNK*CHLEN == T_LEN
__device__ float g_pnum[NCHUNK * NCH];
__device__ float g_pden[NCHUNK * NCH];

// ---------------- helpers ----------------
__device__ __forceinline__ float round_tf32(float x) {
    uint32_t u;
    asm("cvt.rna.tf32.f32 %0, %1;" : "=r"(u) : "f"(x));
    return __uint_as_float(u);
}
__device__ __forceinline__ unsigned int enc_f(float f) {
    unsigned int u = __float_as_uint(f);
    return ((int)u >= 0) ? (u ^ 0x80000000u) : ~u;
}
__device__ __forceinline__ float dec_f(unsigned int k) {
    unsigned int u = (k & 0x80000000u) ? (k ^ 0x80000000u) : ~k;
    return __uint_as_float(u);
}
__device__ __forceinline__ void mma8(float c[4], const uint32_t a[4], const uint32_t b[2]) {
    asm volatile(
        "mma.sync.aligned.m16n8k8.row.col.f32.tf32.tf32.f32 "
        "{%0,%1,%2,%3}, {%4,%5,%6,%7}, {%8,%9}, {%0,%1,%2,%3};\n"
        : "+f"(c[0]), "+f"(c[1]), "+f"(c[2]), "+f"(c[3])
        : "r"(a[0]), "r"(a[1]), "r"(a[2]), "r"(a[3]),
          "r"(b[0]), "r"(b[1]));
}
__device__ __forceinline__ void cp16(uint32_t dst, const void* src) {
    asm volatile("cp.async.cg.shared.global [%0], [%1], 16;" :: "r"(dst), "l"(src));
}
__device__ __forceinline__ void cp_commit() {
    asm volatile("cp.async.commit_group;" ::: "memory");
}
__device__ __forceinline__ uint32_t smem_to_u32(const void* p) {
    uint32_t a;
    asm("{ .reg .u64 t; cvta.to.shared.u64 t, %1; cvt.u32.u64 %0, t; }" : "=r"(a) : "l"(p));
    return a;
}

// ---------------- prep1: pos_bias colmax partials + tf32 rounding of GEMM inputs ----
// blocks 0..255            : colmax partials (2 x 128 layout)
// blocks 256..256+7167     : round 1,835,008 float4 (query,key,value,Wq,Wk,Wv,Wo)
__global__ __launch_bounds__(256) void prep1_kernel(
    const float* __restrict__ pb,
    const float* __restrict__ query, const float* __restrict__ key, const float* __restrict__ value,
    const float* __restrict__ Wq, const float* __restrict__ Wk, const float* __restrict__ Wv,
    const float* __restrict__ Wo)
{
    int blk = blockIdx.x;
    if (blk < 256) {
        int bx = blk & 1, by = blk >> 1;
        int c4 = (bx * 256 + threadIdx.x) << 2;
        int r0 = by << 4;
        float4 m = make_float4(-1e30f, -1e30f, -1e30f, -1e30f);
#pragma unroll
        for (int i = 0; i < 16; i++) {
            float4 v = *reinterpret_cast<const float4*>(&pb[(size_t)(r0 + i) * T_LEN + c4]);
            m.x = fmaxf(m.x, v.x); m.y = fmaxf(m.y, v.y);
            m.z = fmaxf(m.z, v.z); m.w = fmaxf(m.w, v.w);
        }
        *reinterpret_cast<float4*>(&g_colmax_part[by * T_LEN + c4]) = m;
        return;
    }
    int i = (blk - 256) * 256 + threadIdx.x;   // float4 index
    const float4* src;
    float4* dst;
    if (i < 524288)       { src = (const float4*)query; dst = (float4*)g_csn; }
    else if (i < 1048576) { src = (const float4*)key   - 524288; dst = (float4*)g_csd - 524288; }
    else if (i < 1572864) { src = (const float4*)value - 1048576; dst = (float4*)g_ek - 1048576; }
    else if (i < 1638400) { src = (const float4*)Wq - 1572864; dst = (float4*)g_wr - 1572864; }
    else if (i < 1703936) { src = (const float4*)Wk - 1638400; dst = (float4*)(g_wr + 262144) - 1638400; }
    else if (i < 1769472) { src = (const float4*)Wv - 1703936; dst = (float4*)(g_wr + 524288) - 1703936; }
    else                  { src = (const float4*)Wo - 1769472; dst = (float4*)g_wor - 1769472; }
    float4 v = src[i];
    v.x = round_tf32(v.x); v.y = round_tf32(v.y);
    v.z = round_tf32(v.z); v.w = round_tf32(v.w);
    dst[i] = v;
}

// ---------------- prep2: epb table + colmax final + mlu zero ----------------
// blocks 0..255 : epb (65536 entries)
// blocks 256,257: colmax reduce
// block 258     : zero g_mlu
__global__ __launch_bounds__(256) void prep2_kernel(const float* __restrict__ pb) {
    int blk = blockIdx.x;
    if (blk < 256) {
        int id = blk * 256 + threadIdx.x;
        int t = id >> 5, j = id & 31;
        int idx = t - (S_WIN - 1) + j;
        g_epb[id] = (idx >= 0) ? __expf(pb[(size_t)t * T_LEN + idx]) : 0.0f;
        return;
    }
    if (blk < 258) {
        int c4 = ((blk - 256) * 256 + threadIdx.x) << 2;
        float4 m = make_float4(-1e30f, -1e30f, -1e30f, -1e30f);
#pragma unroll 8
        for (int i = 0; i < 128; i++) {
            float4 v = *reinterpret_cast<float4*>(&g_colmax_part[i * T_LEN + c4]);
            m.x = fmaxf(m.x, v.x); m.y = fmaxf(m.y, v.y);
            m.z = fmaxf(m.z, v.z); m.w = fmaxf(m.w, v.w);
        }
        *reinterpret_cast<float4*>(&g_colmax[c4]) = m;
        return;
    }
    g_mlu[threadIdx.x] = 0u;
    g_mlu[threadIdx.x + 256] = 0u;
}

// ---------------- pipelined tf32 GEMM (inputs pre-rounded, no cvt in loop) -----------
#define GBM 128
#define GBN 128
#define GBK 32
#define GSTG 3
#define NKT 16                    // 512/GBK
#define PADK 36
#define A_STG (GBM * PADK)
#define B_STG (GBN * PADK)
#define STG_FLOATS (A_STG + B_STG)
#define GEMM_SMEM (GSTG * STG_FLOATS * 4)   // 110,592 B

__device__ __forceinline__ void ld_stage(uint32_t sb, const float* __restrict__ A,
                                         const float* __restrict__ W,
                                         int bm, int bn, int kt, int tid) {
    uint32_t base = sb + (uint32_t)((kt % GSTG) * STG_FLOATS * 4);
#pragma unroll
    for (int i = 0; i < 4; i++) {
        int chunk = tid + i * 256;
        int row = chunk >> 3, c16 = chunk & 7;
        cp16(base + (uint32_t)(row * PADK + c16 * 4) * 4,
             &A[(size_t)(bm * GBM + row) * 512 + kt * GBK + c16 * 4]);
    }
    base += A_STG * 4;
#pragma unroll
    for (int i = 0; i < 4; i++) {
        int chunk = tid + i * 256;
        int row = chunk >> 3, c16 = chunk & 7;
        cp16(base + (uint32_t)(row * PADK + c16 * 4) * 4,
             &W[(size_t)(bn * GBN + row) * 512 + kt * GBK + c16 * 4]);
    }
    cp_commit();
}

__global__ void __launch_bounds__(256, 2) gemm_qkv(
    const float* __restrict__ A0, const float* __restrict__ A1, const float* __restrict__ A2,
    const float* __restrict__ Wr,
    const float* __restrict__ B0, const float* __restrict__ B1, const float* __restrict__ B2,
    float* __restrict__ C0, float* __restrict__ C1, float* __restrict__ C2)
{
    extern __shared__ float smem[];
    const uint32_t sb = smem_to_u32(smem);
    const int tid  = threadIdx.x;
    const int lane = tid & 31;
    const int wid  = tid >> 5;
    const int wm   = wid & 1;        // 2 warps in m
    const int wn   = wid >> 1;       // 4 warps in n
    const int bm   = blockIdx.x, bn = blockIdx.y;
    const int z    = blockIdx.z;

    const float* A    = (z == 0) ? A0 : (z == 1) ? A1 : A2;
    const float* W    = Wr + (size_t)z * 262144;
    const float* bias = (z == 0) ? B0 : (z == 1) ? B1 : B2;
    float*       C    = (z == 0) ? C0 : (z == 1) ? C1 : C2;

    const int r_fr = lane >> 2;
    const int c_fr = lane & 3;

    float acc[4][4][4];
#pragma unroll
    for (int mt = 0; mt < 4; mt++)
#pragma unroll
        for (int nt = 0; nt < 4; nt++)
#pragma unroll
            for (int i = 0; i < 4; i++) acc[mt][nt][i] = 0.0f;

    ld_stage(sb, A, W, bm, bn, 0, tid);
    ld_stage(sb, A, W, bm, bn, 1, tid);

#pragma unroll 1
    for (int kt = 0; kt < NKT; kt++) {
        if (kt < NKT - 2) asm volatile("cp.async.wait_group 1;" ::: "memory");
        else              asm volatile("cp.async.wait_group 0;" ::: "memory");
        __syncthreads();

        if (kt + 2 < NKT) ld_stage(sb, A, W, bm, bn, kt + 2, tid);

        const float* As = smem + (kt % GSTG) * STG_FLOATS;
        const float* Bs = As + A_STG;
#pragma unroll
        for (int ks = 0; ks < 4; ks++) {
            const int kk = ks * 8;
            uint32_t a[4][4], b[4][2];
#pragma unroll
            for (int mt = 0; mt < 4; mt++) {
                int m0 = wm * 64 + mt * 16 + r_fr;
                a[mt][0] = __float_as_uint(As[(m0    ) * PADK + kk + c_fr    ]);
                a[mt][1] = __float_as_uint(As[(m0 + 8) * PADK + kk + c_fr    ]);
                a[mt][2] = __float_as_uint(As[(m0    ) * PADK + kk + c_fr + 4]);
                a[mt][3] = __float_as_uint(As[(m0 + 8) * PADK + kk + c_fr + 4]);
            }
#pragma unroll
            for (int nt = 0; nt < 4; nt++) {
                int n0 = wn * 32 + nt * 8 + r_fr;
                b[nt][0] = __float_as_uint(Bs[n0 * PADK + kk + c_fr    ]);
                b[nt][1] = __float_as_uint(Bs[n0 * PADK + kk + c_fr + 4]);
            }
#pragma unroll
            for (int mt = 0; mt < 4; mt++)
#pragma unroll
                for (int nt = 0; nt < 4; nt++)
                    mma8(acc[mt][nt], a[mt], b[nt]);
        }
    }

    const int c2 = (lane & 3) * 2;
#pragma unroll
    for (int mt = 0; mt < 4; mt++) {
#pragma unroll
        for (int nt = 0; nt < 4; nt++) {
            int row = bm * GBM + wm * 64 + mt * 16 + r_fr;
            int col = bn * GBN + wn * 32 + nt * 8 + c2;
            float b0 = bias[col], b1 = bias[col + 1];
            *reinterpret_cast<float2*>(&C[(size_t)row * 512 + col]) =
                make_float2(acc[mt][nt][0] + b0, acc[mt][nt][1] + b1);
            *reinterpret_cast<float2*>(&C[(size_t)(row + 8) * 512 + col]) =
                make_float2(acc[mt][nt][2] + b0, acc[mt][nt][3] + b1);
        }
    }
}

// ---------------- BM=64 GEMM for the output projection (all CTAs resident) ----------
#define OBM 64
#define OA_STG (OBM * PADK)
#define OSTG_FLOATS (OA_STG + B_STG)
#define OGEMM_SMEM (GSTG * OSTG_FLOATS * 4)   // 82,944 B

__device__ __forceinline__ void ld_stage_o(uint32_t sb, const float* __restrict__ A,
                                           const float* __restrict__ W,
                                           int bm, int bn, int kt, int tid) {
    uint32_t base = sb + (uint32_t)((kt % GSTG) * OSTG_FLOATS * 4);
#pragma unroll
    for (int i = 0; i < 4; i++) {
        int chunk = tid + i * 128;             // 512 chunks: 64 rows x 8
        int row = chunk >> 3, c16 = chunk & 7;
        cp16(base + (uint32_t)(row * PADK + c16 * 4) * 4,
             &A[(size_t)(bm * OBM + row) * 512 + kt * GBK + c16 * 4]);
    }
    base += OA_STG * 4;
#pragma unroll
    for (int i = 0; i < 8; i++) {
        int chunk = tid + i * 128;             // 1024 chunks: 128 rows x 8
        int row = chunk >> 3, c16 = chunk & 7;
        cp16(base + (uint32_t)(row * PADK + c16 * 4) * 4,
             &W[(size_t)(bn * GBN + row) * 512 + kt * GBK + c16 * 4]);
    }
    cp_commit();
}

__global__ void __launch_bounds__(128, 2) gemm_o(
    const float* __restrict__ A, const float* __restrict__ W,
    const float* __restrict__ bias, float* __restrict__ C)
{
    extern __shared__ float smem[];
    const uint32_t sb = smem_to_u32(smem);
    const int tid  = threadIdx.x;
    const int lane = tid & 31;
    const int wn   = tid >> 5;       // 4 warps, all in n
    const int bm   = blockIdx.x, bn = blockIdx.y;

    const int r_fr = lane >> 2;
    const int c_fr = lane & 3;

    float acc[4][4][4];
#pragma unroll
    for (int mt = 0; mt < 4; mt++)
#pragma unroll
        for (int nt = 0; nt < 4; nt++)
#pragma unroll
            for (int i = 0; i < 4; i++) acc[mt][nt][i] = 0.0f;

    ld_stage_o(sb, A, W, bm, bn, 0, tid);
    ld_stage_o(sb, A, W, bm, bn, 1, tid);

#pragma unroll 1
    for (int kt = 0; kt < NKT; kt++) {
        if (kt < NKT - 2) asm volatile("cp.async.wait_group 1;" ::: "memory");
        else              asm volatile("cp.async.wait_group 0;" ::: "memory");
        __syncthreads();

        if (kt + 2 < NKT) ld_stage_o(sb, A, W, bm, bn, kt + 2, tid);

        const float* As = smem + (kt % GSTG) * OSTG_FLOATS;
        const float* Bs = As + OA_STG;
#pragma unroll
        for (int ks = 0; ks < 4; ks++) {
            const int kk = ks * 8;
            uint32_t a[4][4], b[4][2];
#pragma unroll
            for (int mt = 0; mt < 4; mt++) {
                int m0 = mt * 16 + r_fr;
                a[mt][0] = __float_as_uint(As[(m0    ) * PADK + kk + c_fr    ]);
                a[mt][1] = __float_as_uint(As[(m0 + 8) * PADK + kk + c_fr    ]);
                a[mt][2] = __float_as_uint(As[(m0    ) * PADK + kk + c_fr + 4]);
                a[mt][3] = __float_as_uint(As[(m0 + 8) * PADK + kk + c_fr + 4]);
            }
#pragma unroll
            for (int nt = 0; nt < 4; nt++) {
                int n0 = wn * 32 + nt * 8 + r_fr;
                b[nt][0] = __float_as_uint(Bs[n0 * PADK + kk + c_fr    ]);
                b[nt][1] = __float_as_uint(Bs[n0 * PADK + kk + c_fr + 4]);
            }
#pragma unroll
            for (int mt = 0; mt < 4; mt++)
#pragma unroll
                for (int nt = 0; nt < 4; nt++)
                    mma8(acc[mt][nt], a[mt], b[nt]);
        }
    }

    const int c2 = (lane & 3) * 2;
#pragma unroll
    for (int mt = 0; mt < 4; mt++) {
#pragma unroll
        for (int nt = 0; nt < 4; nt++) {
            int row = bm * OBM + mt * 16 + r_fr;
            int col = bn * GBN + wn * 32 + nt * 8 + c2;
            float b0 = bias[col], b1 = bias[col + 1];
            *reinterpret_cast<float2*>(&C[(size_t)row * 512 + col]) =
                make_float2(acc[mt][nt][0] + b0, acc[mt][nt][1] + b1);
            *reinterpret_cast<float2*>(&C[(size_t)(row + 8) * 512 + col]) =
                make_float2(acc[mt][nt][2] + b0, acc[mt][nt][3] + b1);
        }
    }
}

// ---------------- max_logit via atomicMax on encoded bits (batch 0 only) ------------
__global__ void ml_kernel() {
    int d  = threadIdx.x;           // 512
    int t0 = blockIdx.x * 32;       // 64 blocks
    float m = -1e30f;
#pragma unroll 4
    for (int i = 0; i < 32; i++) {
        int t = t0 + i;
        float kv = g_k[(size_t)t * NCH + d];
        float cm = g_colmax[t];
        m = fmaxf(m, fmaxf(kv, kv + cm));
    }
    atomicMax(&g_mlu[d], enc_f(m));
}

// ---------------- chunked scan of ek, ek*v over T ----------------
__global__ void scanA_kernel() {
    int ch = blockIdx.x * 256 + threadIdx.x;
    int t0 = blockIdx.y * CHLEN;
    float ml = dec_f(g_mlu[ch & (D_MODEL - 1)]);
    float sn = 0.f, sd = 0.f;
#pragma unroll 4
    for (int i = 0; i < CHLEN; i++) {
        int t = t0 + i;
        float e = __expf(g_k[(size_t)t * NCH + ch] - ml);
        sd += e;
        sn += e * g_v[(size_t)t * NCH + ch];
    }
    g_pden[blockIdx.y * NCH + ch] = sd;
    g_pnum[blockIdx.y * NCH + ch] = sn;
}

__global__ void scanB_kernel() {
    int ch = blockIdx.x * 256 + threadIdx.x;
    float rd = 0.f, rn = 0.f;
#pragma unroll 4
    for (int c = 0; c < NCHUNK; c++) {
        int i = c * NCH + ch;
        float td = g_pden[i], tn = g_pnum[i];
        g_pden[i] = rd; g_pnum[i] = rn;
        rd += td; rn += tn;
    }
}

__global__ void scanC_kernel() {
    int ch = blockIdx.x * 256 + threadIdx.x;
    int t0 = blockIdx.y * CHLEN;
    float ml = dec_f(g_mlu[ch & (D_MODEL - 1)]);
    float rn = g_pnum[blockIdx.y * NCH + ch];
    float rd = g_pden[blockIdx.y * NCH + ch];
#pragma unroll 4
    for (int i = 0; i < CHLEN; i++) {
        int t = t0 + i;
        float e = __expf(g_k[(size_t)t * NCH + ch] - ml);
        g_ek[(size_t)t * NCH + ch] = e;
        rd += e;
        rn += e * g_v[(size_t)t * NCH + ch];
        g_csd[(size_t)t * NCH + ch] = rd;
        g_csn[(size_t)t * NCH + ch] = rn;
    }
}

// ---------------- AFT local window + gating (FMA-only; y written tf32-rounded) ------
__global__ __launch_bounds__(256) void aft_kernel() {
    __shared__ float2 s_ek[63 * 32];
    __shared__ float2 s_v [63 * 32];
    __shared__ float  s_epb[32 * 32];

    const int tid = threadIdx.x;
    const int w = tid >> 5, l = tid & 31;
    const int t0 = blockIdx.x << 5;
    const int chp = blockIdx.y * 32 + l;

    const float2* ek2 = reinterpret_cast<const float2*>(g_ek);
    const float2* v2g = reinterpret_cast<const float2*>(g_v);

    for (int i = tid; i < 63 * 32; i += 256) {
        int r = i >> 5, cp = i & 31;
        int gr = t0 - 31 + r;
        float2 e = make_float2(0.f, 0.f), vv = make_float2(0.f, 0.f);
        if (gr >= 0) {
            size_t gi = (size_t)gr * 512 + blockIdx.y * 32 + cp;
            e  = ek2[gi];
            vv = v2g[gi];
        }
        s_ek[i] = e; s_v[i] = vv;
    }
    for (int i = tid; i < 1024; i += 256)
        s_epb[i] = g_epb[t0 * 32 + i];
    __syncthreads();

    const float2* csn2 = reinterpret_cast<const float2*>(g_csn);
    const float2* csd2 = reinterpret_cast<const float2*>(g_csd);
    const float2* q2g  = reinterpret_cast<const float2*>(g_q);
    float2* y2 = reinterpret_cast<float2*>(g_y);

#pragma unroll
    for (int ii = 0; ii < 4; ii++) {
        int tl = w + (ii << 3);
        int t  = t0 + tl;
        float nx = 0.f, ny = 0.f, dx = 0.f, dy = 0.f;
        if (t >= S_WIN) {
            float2 n0 = csn2[(size_t)(t - S_WIN) * 512 + chp];
            float2 d0 = csd2[(size_t)(t - S_WIN) * 512 + chp];
            nx = n0.x; ny = n0.y; dx = d0.x; dy = d0.y;
        }
#pragma unroll 8
        for (int j = 0; j < 32; j++) {
            float  ep = s_epb[(tl << 5) + j];
            float2 e2 = s_ek[((tl + j) << 5) + l];
            float2 vv = s_v [((tl + j) << 5) + l];
            float ex = e2.x * ep, ey = e2.y * ep;
            nx += ex * vv.x; ny += ey * vv.y;
            dx += ex;        dy += ey;
        }
        float2 q = q2g[(size_t)t * 512 + chp];
        float sx = 1.f / (1.f + __expf(-q.x));
        float sy = 1.f / (1.f + __expf(-q.y));
        // write y pre-rounded to tf32 so gemm_o needs no conversion
        y2[(size_t)t * 512 + chp] =
            make_float2(round_tf32(sx * nx / dx), round_tf32(sy * ny / dy));
    }
}

// ---------------- launch ----------------
extern "C" void kernel_launch(void* const* d_in, const int* in_sizes, int n_in,
                              void* d_out, int out_size) {
    const float* query = (const float*)d_in[0];
    const float* key   = (const float*)d_in[1];
    const float* value = (const float*)d_in[2];
    const float* Wq    = (const float*)d_in[3];
    const float* bq    = (const float*)d_in[4];
    const float* Wk    = (const float*)d_in[5];
    const float* bk    = (const float*)d_in[6];
    const float* Wv    = (const float*)d_in[7];
    const float* bv    = (const float*)d_in[8];
    const float* pb    = (const float*)d_in[9];
    const float* Wo    = (const float*)d_in[10];
    const float* bo    = (const float*)d_in[11];
    float* out = (float*)d_out;

    float *pq, *pk, *pv, *py, *pqr, *pkr, *pvr, *pwr, *pwor;
    cudaGetSymbolAddress((void**)&pq,  g_q);
    cudaGetSymbolAddress((void**)&pk,  g_k);
    cudaGetSymbolAddress((void**)&pv,  g_v);
    cudaGetSymbolAddress((void**)&py,  g_y);
    cudaGetSymbolAddress((void**)&pqr, g_csn);
    cudaGetSymbolAddress((void**)&pkr, g_csd);
    cudaGetSymbolAddress((void**)&pvr, g_ek);
    cudaGetSymbolAddress((void**)&pwr, g_wr);
    cudaGetSymbolAddress((void**)&pwor, g_wor);

    cudaFuncSetAttribute(gemm_qkv, cudaFuncAttributeMaxDynamicSharedMemorySize, GEMM_SMEM);
    cudaFuncSetAttribute(gemm_o,   cudaFuncAttributeMaxDynamicSharedMemorySize, OGEMM_SMEM);

    // 1. round inputs to tf32 + pos_bias colmax partials
    prep1_kernel<<<256 + 7168, 256>>>(pb, query, key, value, Wq, Wk, Wv, Wo);
    // 2. epb table + colmax final + mlu zero
    prep2_kernel<<<259, 256>>>(pb);

    // 3. q/k/v projections (pre-rounded operands)
    dim3 ggrid3(M_ROWS / GBM, D_MODEL / GBN, 3);   // (32, 4, 3)
    gemm_qkv<<<ggrid3, 256, GEMM_SMEM>>>(pqr, pkr, pvr, pwr,
                                         bq, bk, bv,
                                         pq, pk, pv);

    // 4. max_logit
    ml_kernel<<<64, 512>>>();

    // 5-7. chunked scans (overwrite the rounded-input scratch, now free)
    scanA_kernel<<<dim3(4, NCHUNK), 256>>>();
    scanB_kernel<<<4, 256>>>();
    scanC_kernel<<<dim3(4, NCHUNK), 256>>>();

    // 8. AFT window + gating (writes tf32-rounded y)
    aft_kernel<<<dim3(64, 16), 256>>>();

    // 9. output projection
    dim3 ogrid(M_ROWS / OBM, D_MODEL / GBN);       // (64, 4)
    gemm_o<<<ogrid, 128, OGEMM_SMEM>>>(py, pwor, bo, out);
}

// round 5
// speedup vs baseline: 1.9282x; 1.1671x over previous
#include <cuda_runtime.h>
#include <cuda_fp16.h>
#include <cstdint>

// ---------------- problem constants ----------------
#define T_LEN   2048
#define BATCH   2
#define D_MODEL 512
#define S_WIN   32
#define M_ROWS  4096           // T*B
#define NCH     1024           // B*D channels

// ---------------- scratch (no allocation allowed) ----------------
__device__ float g_q[M_ROWS * D_MODEL];
__device__ float g_k[M_ROWS * D_MODEL];
__device__ float g_v[M_ROWS * D_MODEL];
__device__ float g_csn[M_ROWS * D_MODEL];
__device__ float g_csd[M_ROWS * D_MODEL];
__device__ float g_ek[M_ROWS * D_MODEL];
__device__ __half g_hx[3 * M_ROWS * D_MODEL];     // fp16 rounded query,key,value
__device__ __half g_hw[4 * D_MODEL * D_MODEL];    // fp16 rounded Wq,Wk,Wv,Wo
__device__ __half g_hy[M_ROWS * D_MODEL];         // fp16 y (gemm_o input)
__device__ float g_colmax_part[128 * T_LEN];
__device__ float g_colmax[T_LEN];
__device__ unsigned int g_mlu[D_MODEL];
__device__ float g_epb[T_LEN * S_WIN];

#define NCHUNK 64
#define CHLEN  32              // NCHUNK*CHLEN == T_LEN
__device__ float g_pnum[NCHUNK * NCH];
__device__ float g_pden[NCHUNK * NCH];

// ---------------- helpers ----------------
__device__ __forceinline__ unsigned int enc_f(float f) {
    unsigned int u = __float_as_uint(f);
    return ((int)u >= 0) ? (u ^ 0x80000000u) : ~u;
}
__device__ __forceinline__ float dec_f(unsigned int k) {
    unsigned int u = (k & 0x80000000u) ? (k ^ 0x80000000u) : ~k;
    return __uint_as_float(u);
}
__device__ __forceinline__ void mma16(float c[4], const uint32_t a[4], const uint32_t b[2]) {
    asm volatile(
        "mma.sync.aligned.m16n8k16.row.col.f32.f16.f16.f32 "
        "{%0,%1,%2,%3}, {%4,%5,%6,%7}, {%8,%9}, {%0,%1,%2,%3};\n"
        : "+f"(c[0]), "+f"(c[1]), "+f"(c[2]), "+f"(c[3])
        : "r"(a[0]), "r"(a[1]), "r"(a[2]), "r"(a[3]),
          "r"(b[0]), "r"(b[1]));
}
__device__ __forceinline__ void cp16(uint32_t dst, const void* src) {
    asm volatile("cp.async.cg.shared.global [%0], [%1], 16;" :: "r"(dst), "l"(src));
}
__device__ __forceinline__ void cp_commit() {
    asm volatile("cp.async.commit_group;" ::: "memory");
}
__device__ __forceinline__ uint32_t smem_to_u32(const void* p) {
    uint32_t a;
    asm("{ .reg .u64 t; cvta.to.shared.u64 t, %1; cvt.u32.u64 %0, t; }" : "=r"(a) : "l"(p));
    return a;
}
__device__ __forceinline__ uint32_t pack_h2(float a, float b) {
    __half2 h = __floats2half2_rn(a, b);
    return *reinterpret_cast<uint32_t*>(&h);
}

// ---------------- prep1: pos_bias colmax partials + fp16 rounding of GEMM inputs ----
// blocks 0..255         : colmax partials
// blocks 256..256+7167  : convert 1,835,008 float4 -> half4 (q,k,v,Wq,Wk,Wv,Wo)
__global__ __launch_bounds__(256) void prep1_kernel(
    const float* __restrict__ pb,
    const float* __restrict__ query, const float* __restrict__ key, const float* __restrict__ value,
    const float* __restrict__ Wq, const float* __restrict__ Wk, const float* __restrict__ Wv,
    const float* __restrict__ Wo)
{
    int blk = blockIdx.x;
    if (blk < 256) {
        int bx = blk & 1, by = blk >> 1;
        int c4 = (bx * 256 + threadIdx.x) << 2;
        int r0 = by << 4;
        float4 m = make_float4(-1e30f, -1e30f, -1e30f, -1e30f);
#pragma unroll
        for (int i = 0; i < 16; i++) {
            float4 v = *reinterpret_cast<const float4*>(&pb[(size_t)(r0 + i) * T_LEN + c4]);
            m.x = fmaxf(m.x, v.x); m.y = fmaxf(m.y, v.y);
            m.z = fmaxf(m.z, v.z); m.w = fmaxf(m.w, v.w);
        }
        *reinterpret_cast<float4*>(&g_colmax_part[by * T_LEN + c4]) = m;
        return;
    }
    int i = (blk - 256) * 256 + threadIdx.x;   // float4 index
    const float4* src;
    __half* dstbase;
    int j;
    if (i < 524288)       { src = (const float4*)query; dstbase = g_hx;                j = i; }
    else if (i < 1048576) { src = (const float4*)key;   dstbase = g_hx + 2097152;      j = i - 524288; }
    else if (i < 1572864) { src = (const float4*)value; dstbase = g_hx + 4194304;      j = i - 1048576; }
    else if (i < 1638400) { src = (const float4*)Wq;    dstbase = g_hw;                j = i - 1572864; }
    else if (i < 1703936) { src = (const float4*)Wk;    dstbase = g_hw + 262144;       j = i - 1638400; }
    else if (i < 1769472) { src = (const float4*)Wv;    dstbase = g_hw + 524288;       j = i - 1703936; }
    else                  { src = (const float4*)Wo;    dstbase = g_hw + 786432;       j = i - 1769472; }
    float4 v = src[j];
    uint2 h;
    h.x = pack_h2(v.x, v.y);
    h.y = pack_h2(v.z, v.w);
    *reinterpret_cast<uint2*>(dstbase + (size_t)j * 4) = h;
}

// ---------------- prep2: epb table + colmax final + mlu zero ----------------
__global__ __launch_bounds__(256) void prep2_kernel(const float* __restrict__ pb) {
    int blk = blockIdx.x;
    if (blk < 256) {
        int id = blk * 256 + threadIdx.x;
        int t = id >> 5, j = id & 31;
        int idx = t - (S_WIN - 1) + j;
        g_epb[id] = (idx >= 0) ? __expf(pb[(size_t)t * T_LEN + idx]) : 0.0f;
        return;
    }
    if (blk < 258) {
        int c4 = ((blk - 256) * 256 + threadIdx.x) << 2;
        float4 m = make_float4(-1e30f, -1e30f, -1e30f, -1e30f);
#pragma unroll 8
        for (int i = 0; i < 128; i++) {
            float4 v = *reinterpret_cast<float4*>(&g_colmax_part[i * T_LEN + c4]);
            m.x = fmaxf(m.x, v.x); m.y = fmaxf(m.y, v.y);
            m.z = fmaxf(m.z, v.z); m.w = fmaxf(m.w, v.w);
        }
        *reinterpret_cast<float4*>(&g_colmax[c4]) = m;
        return;
    }
    g_mlu[threadIdx.x] = 0u;
    g_mlu[threadIdx.x + 256] = 0u;
}

// ---------------- fp16 pipelined GEMM: C[M,512] = A[M,512] @ W[512,512]^T + bias ----
#define GBM 128
#define GBN 128
#define GBK 64
#define GSTG 3
#define NKT 8                       // 512/GBK
#define PADH 72                     // halves per smem row (144 B)
#define A_HALVES (GBM * PADH)
#define STG_HALVES (2 * A_HALVES)   // A + B
#define STG_BYTES (STG_HALVES * 2)  // 36,864 B
#define GEMM_SMEM (GSTG * STG_BYTES) // 110,592 B

__device__ __forceinline__ void ld_stage(uint32_t sb, const __half* __restrict__ A,
                                         const __half* __restrict__ W,
                                         int bm, int bn, int kt, int tid) {
    uint32_t base = sb + (uint32_t)((kt % GSTG) * STG_BYTES);
#pragma unroll
    for (int i = 0; i < 4; i++) {
        int chunk = tid + i * 256;             // 1024 chunks: 128 rows x 8x16B
        int row = chunk >> 3, c16 = chunk & 7;
        cp16(base + (uint32_t)(row * 144 + c16 * 16),
             &A[(size_t)(bm * GBM + row) * 512 + kt * GBK + c16 * 8]);
    }
    base += A_HALVES * 2;
#pragma unroll
    for (int i = 0; i < 4; i++) {
        int chunk = tid + i * 256;
        int row = chunk >> 3, c16 = chunk & 7;
        cp16(base + (uint32_t)(row * 144 + c16 * 16),
             &W[(size_t)(bn * GBN + row) * 512 + kt * GBK + c16 * 8]);
    }
    cp_commit();
}

__global__ void __launch_bounds__(256, 2) gemm_qkv(
    const __half* __restrict__ X, const __half* __restrict__ Wh,
    const float* __restrict__ B0, const float* __restrict__ B1, const float* __restrict__ B2,
    float* __restrict__ C0, float* __restrict__ C1, float* __restrict__ C2)
{
    extern __shared__ char smem_c[];
    const uint32_t sb = smem_to_u32(smem_c);
    const int tid  = threadIdx.x;
    const int lane = tid & 31;
    const int wid  = tid >> 5;
    const int wm   = wid & 1;        // 2 warps in m
    const int wn   = wid >> 1;       // 4 warps in n
    const int bm   = blockIdx.x, bn = blockIdx.y;
    const int z    = blockIdx.z;

    const __half* A    = X  + (size_t)z * (M_ROWS * D_MODEL);
    const __half* W    = Wh + (size_t)z * (D_MODEL * D_MODEL);
    const float* bias  = (z == 0) ? B0 : (z == 1) ? B1 : B2;
    float*       C     = (z == 0) ? C0 : (z == 1) ? C1 : C2;

    const int r_fr = lane >> 2;
    const int c_fr = lane & 3;

    float acc[4][4][4];
#pragma unroll
    for (int mt = 0; mt < 4; mt++)
#pragma unroll
        for (int nt = 0; nt < 4; nt++)
#pragma unroll
            for (int i = 0; i < 4; i++) acc[mt][nt][i] = 0.0f;

    ld_stage(sb, A, W, bm, bn, 0, tid);
    ld_stage(sb, A, W, bm, bn, 1, tid);

#pragma unroll 1
    for (int kt = 0; kt < NKT; kt++) {
        if (kt < NKT - 2) asm volatile("cp.async.wait_group 1;" ::: "memory");
        else              asm volatile("cp.async.wait_group 0;" ::: "memory");
        __syncthreads();

        if (kt + 2 < NKT) ld_stage(sb, A, W, bm, bn, kt + 2, tid);

        const __half* As = reinterpret_cast<const __half*>(smem_c) + (kt % GSTG) * STG_HALVES;
        const __half* Bs = As + A_HALVES;
#pragma unroll
        for (int ks = 0; ks < 4; ks++) {
            const int kh = ks * 16;
            uint32_t a[4][4], b[4][2];
#pragma unroll
            for (int mt = 0; mt < 4; mt++) {
                int m0 = wm * 64 + mt * 16 + r_fr;
                a[mt][0] = *reinterpret_cast<const uint32_t*>(&As[(m0    ) * PADH + kh + 2 * c_fr    ]);
                a[mt][1] = *reinterpret_cast<const uint32_t*>(&As[(m0 + 8) * PADH + kh + 2 * c_fr    ]);
                a[mt][2] = *reinterpret_cast<const uint32_t*>(&As[(m0    ) * PADH + kh + 2 * c_fr + 8]);
                a[mt][3] = *reinterpret_cast<const uint32_t*>(&As[(m0 + 8) * PADH + kh + 2 * c_fr + 8]);
            }
#pragma unroll
            for (int nt = 0; nt < 4; nt++) {
                int n0 = wn * 32 + nt * 8 + r_fr;
                b[nt][0] = *reinterpret_cast<const uint32_t*>(&Bs[n0 * PADH + kh + 2 * c_fr    ]);
                b[nt][1] = *reinterpret_cast<const uint32_t*>(&Bs[n0 * PADH + kh + 2 * c_fr + 8]);
            }
#pragma unroll
            for (int mt = 0; mt < 4; mt++)
#pragma unroll
                for (int nt = 0; nt < 4; nt++)
                    mma16(acc[mt][nt], a[mt], b[nt]);
        }
    }

    const int c2 = (lane & 3) * 2;
#pragma unroll
    for (int mt = 0; mt < 4; mt++) {
#pragma unroll
        for (int nt = 0; nt < 4; nt++) {
            int row = bm * GBM + wm * 64 + mt * 16 + r_fr;
            int col = bn * GBN + wn * 32 + nt * 8 + c2;
            float b0 = bias[col], b1 = bias[col + 1];
            *reinterpret_cast<float2*>(&C[(size_t)row * 512 + col]) =
                make_float2(acc[mt][nt][0] + b0, acc[mt][nt][1] + b1);
            *reinterpret_cast<float2*>(&C[(size_t)(row + 8) * 512 + col]) =
                make_float2(acc[mt][nt][2] + b0, acc[mt][nt][3] + b1);
        }
    }
}

// ---------------- BM=64 fp16 GEMM for the output projection ----------------
#define OBM 64
#define OA_HALVES (OBM * PADH)
#define OSTG_HALVES (OA_HALVES + A_HALVES)     // A(64 rows) + B(128 rows)
#define OSTG_BYTES (OSTG_HALVES * 2)           // 27,648 B
#define OGEMM_SMEM (GSTG * OSTG_BYTES)         // 82,944 B

__device__ __forceinline__ void ld_stage_o(uint32_t sb, const __half* __restrict__ A,
                                           const __half* __restrict__ W,
                                           int bm, int bn, int kt, int tid) {
    uint32_t base = sb + (uint32_t)((kt % GSTG) * OSTG_BYTES);
#pragma unroll
    for (int i = 0; i < 4; i++) {
        int chunk = tid + i * 128;             // 512 chunks: 64 rows x 8
        int row = chunk >> 3, c16 = chunk & 7;
        cp16(base + (uint32_t)(row * 144 + c16 * 16),
             &A[(size_t)(bm * OBM + row) * 512 + kt * GBK + c16 * 8]);
    }
    base += OA_HALVES * 2;
#pragma unroll
    for (int i = 0; i < 8; i++) {
        int chunk = tid + i * 128;             // 1024 chunks: 128 rows x 8
        int row = chunk >> 3, c16 = chunk & 7;
        cp16(base + (uint32_t)(row * 144 + c16 * 16),
             &W[(size_t)(bn * GBN + row) * 512 + kt * GBK + c16 * 8]);
    }
    cp_commit();
}

__global__ void __launch_bounds__(128, 2) gemm_o(
    const __half* __restrict__ A, const __half* __restrict__ W,
    const float* __restrict__ bias, float* __restrict__ C)
{
    extern __shared__ char smem_c[];
    const uint32_t sb = smem_to_u32(smem_c);
    const int tid  = threadIdx.x;
    const int lane = tid & 31;
    const int wn   = tid >> 5;       // 4 warps, all in n
    const int bm   = blockIdx.x, bn = blockIdx.y;

    const int r_fr = lane >> 2;
    const int c_fr = lane & 3;

    float acc[4][4][4];
#pragma unroll
    for (int mt = 0; mt < 4; mt++)
#pragma unroll
        for (int nt = 0; nt < 4; nt++)
#pragma unroll
            for (int i = 0; i < 4; i++) acc[mt][nt][i] = 0.0f;

    ld_stage_o(sb, A, W, bm, bn, 0, tid);
    ld_stage_o(sb, A, W, bm, bn, 1, tid);

#pragma unroll 1
    for (int kt = 0; kt < NKT; kt++) {
        if (kt < NKT - 2) asm volatile("cp.async.wait_group 1;" ::: "memory");
        else              asm volatile("cp.async.wait_group 0;" ::: "memory");
        __syncthreads();

        if (kt + 2 < NKT) ld_stage_o(sb, A, W, bm, bn, kt + 2, tid);

        const __half* As = reinterpret_cast<const __half*>(smem_c) + (kt % GSTG) * OSTG_HALVES;
        const __half* Bs = As + OA_HALVES;
#pragma unroll
        for (int ks = 0; ks < 4; ks++) {
            const int kh = ks * 16;
            uint32_t a[4][4], b[4][2];
#pragma unroll
            for (int mt = 0; mt < 4; mt++) {
                int m0 = mt * 16 + r_fr;
                a[mt][0] = *reinterpret_cast<const uint32_t*>(&As[(m0    ) * PADH + kh + 2 * c_fr    ]);
                a[mt][1] = *reinterpret_cast<const uint32_t*>(&As[(m0 + 8) * PADH + kh + 2 * c_fr    ]);
                a[mt][2] = *reinterpret_cast<const uint32_t*>(&As[(m0    ) * PADH + kh + 2 * c_fr + 8]);
                a[mt][3] = *reinterpret_cast<const uint32_t*>(&As[(m0 + 8) * PADH + kh + 2 * c_fr + 8]);
            }
#pragma unroll
            for (int nt = 0; nt < 4; nt++) {
                int n0 = wn * 32 + nt * 8 + r_fr;
                b[nt][0] = *reinterpret_cast<const uint32_t*>(&Bs[n0 * PADH + kh + 2 * c_fr    ]);
                b[nt][1] = *reinterpret_cast<const uint32_t*>(&Bs[n0 * PADH + kh + 2 * c_fr + 8]);
            }
#pragma unroll
            for (int mt = 0; mt < 4; mt++)
#pragma unroll
                for (int nt = 0; nt < 4; nt++)
                    mma16(acc[mt][nt], a[mt], b[nt]);
        }
    }

    const int c2 = (lane & 3) * 2;
#pragma unroll
    for (int mt = 0; mt < 4; mt++) {
#pragma unroll
        for (int nt = 0; nt < 4; nt++) {
            int row = bm * OBM + mt * 16 + r_fr;
            int col = bn * GBN + wn * 32 + nt * 8 + c2;
            float b0 = bias[col], b1 = bias[col + 1];
            *reinterpret_cast<float2*>(&C[(size_t)row * 512 + col]) =
                make_float2(acc[mt][nt][0] + b0, acc[mt][nt][1] + b1);
            *reinterpret_cast<float2*>(&C[(size_t)(row + 8) * 512 + col]) =
                make_float2(acc[mt][nt][2] + b0, acc[mt][nt][3] + b1);
        }
    }
}

// ---------------- max_logit via atomicMax (batch 0 only), float4 over d -------------
__global__ void ml_kernel() {
    int d4 = threadIdx.x << 2;      // 128 threads -> 512 d
    int t0 = blockIdx.x * 8;        // 256 blocks
    float4 m = make_float4(-1e30f, -1e30f, -1e30f, -1e30f);
#pragma unroll
    for (int i = 0; i < 8; i++) {
        int t = t0 + i;
        float4 kv = *reinterpret_cast<const float4*>(&g_k[(size_t)t * NCH + d4]);
        float cm = g_colmax[t];
        m.x = fmaxf(m.x, fmaxf(kv.x, kv.x + cm));
        m.y = fmaxf(m.y, fmaxf(kv.y, kv.y + cm));
        m.z = fmaxf(m.z, fmaxf(kv.z, kv.z + cm));
        m.w = fmaxf(m.w, fmaxf(kv.w, kv.w + cm));
    }
    atomicMax(&g_mlu[d4    ], enc_f(m.x));
    atomicMax(&g_mlu[d4 + 1], enc_f(m.y));
    atomicMax(&g_mlu[d4 + 2], enc_f(m.z));
    atomicMax(&g_mlu[d4 + 3], enc_f(m.w));
}

// ---------------- chunked scan of ek, ek*v over T ----------------
__global__ void scanA_kernel() {
    int ch = blockIdx.x * 256 + threadIdx.x;
    int t0 = blockIdx.y * CHLEN;
    float ml = dec_f(g_mlu[ch & (D_MODEL - 1)]);
    float sn = 0.f, sd = 0.f;
#pragma unroll 4
    for (int i = 0; i < CHLEN; i++) {
        int t = t0 + i;
        float e = __expf(g_k[(size_t)t * NCH + ch] - ml);
        sd += e;
        sn += e * g_v[(size_t)t * NCH + ch];
    }
    g_pden[blockIdx.y * NCH + ch] = sd;
    g_pnum[blockIdx.y * NCH + ch] = sn;
}

__global__ void scanB_kernel() {
    int ch = blockIdx.x * 256 + threadIdx.x;
    float rd = 0.f, rn = 0.f;
#pragma unroll 4
    for (int c = 0; c < NCHUNK; c++) {
        int i = c * NCH + ch;
        float td = g_pden[i], tn = g_pnum[i];
        g_pden[i] = rd; g_pnum[i] = rn;
        rd += td; rn += tn;
    }
}

__global__ void scanC_kernel() {
    int ch = blockIdx.x * 256 + threadIdx.x;
    int t0 = blockIdx.y * CHLEN;
    float ml = dec_f(g_mlu[ch & (D_MODEL - 1)]);
    float rn = g_pnum[blockIdx.y * NCH + ch];
    float rd = g_pden[blockIdx.y * NCH + ch];
#pragma unroll 4
    for (int i = 0; i < CHLEN; i++) {
        int t = t0 + i;
        float e = __expf(g_k[(size_t)t * NCH + ch] - ml);
        g_ek[(size_t)t * NCH + ch] = e;
        rd += e;
        rn += e * g_v[(size_t)t * NCH + ch];
        g_csd[(size_t)t * NCH + ch] = rd;
        g_csn[(size_t)t * NCH + ch] = rn;
    }
}

// ---------------- AFT local window + gating (FMA-only; y written fp16) --------------
__global__ __launch_bounds__(256) void aft_kernel() {
    __shared__ float2 s_ek[63 * 32];
    __shared__ float2 s_v [63 * 32];
    __shared__ float  s_epb[32 * 32];

    const int tid = threadIdx.x;
    const int w = tid >> 5, l = tid & 31;
    const int t0 = blockIdx.x << 5;
    const int chp = blockIdx.y * 32 + l;

    const float2* ek2 = reinterpret_cast<const float2*>(g_ek);
    const float2* v2g = reinterpret_cast<const float2*>(g_v);

    for (int i = tid; i < 63 * 32; i += 256) {
        int r = i >> 5, cp = i & 31;
        int gr = t0 - 31 + r;
        float2 e = make_float2(0.f, 0.f), vv = make_float2(0.f, 0.f);
        if (gr >= 0) {
            size_t gi = (size_t)gr * 512 + blockIdx.y * 32 + cp;
            e  = ek2[gi];
            vv = v2g[gi];
        }
        s_ek[i] = e; s_v[i] = vv;
    }
    for (int i = tid; i < 1024; i += 256)
        s_epb[i] = g_epb[t0 * 32 + i];
    __syncthreads();

    const float2* csn2 = reinterpret_cast<const float2*>(g_csn);
    const float2* csd2 = reinterpret_cast<const float2*>(g_csd);
    const float2* q2g  = reinterpret_cast<const float2*>(g_q);
    __half2* y2 = reinterpret_cast<__half2*>(g_hy);

#pragma unroll
    for (int ii = 0; ii < 4; ii++) {
        int tl = w + (ii << 3);
        int t  = t0 + tl;
        float nx = 0.f, ny = 0.f, dx = 0.f, dy = 0.f;
        if (t >= S_WIN) {
            float2 n0 = csn2[(size_t)(t - S_WIN) * 512 + chp];
            float2 d0 = csd2[(size_t)(t - S_WIN) * 512 + chp];
            nx = n0.x; ny = n0.y; dx = d0.x; dy = d0.y;
        }
#pragma unroll 8
        for (int j = 0; j < 32; j++) {
            float  ep = s_epb[(tl << 5) + j];
            float2 e2 = s_ek[((tl + j) << 5) + l];
            float2 vv = s_v [((tl + j) << 5) + l];
            float ex = e2.x * ep, ey = e2.y * ep;
            nx += ex * vv.x; ny += ey * vv.y;
            dx += ex;        dy += ey;
        }
        float2 q = q2g[(size_t)t * 512 + chp];
        float sx = 1.f / (1.f + __expf(-q.x));
        float sy = 1.f / (1.f + __expf(-q.y));
        y2[(size_t)t * 512 + chp] = __floats2half2_rn(sx * nx / dx, sy * ny / dy);
    }
}

// ---------------- launch ----------------
extern "C" void kernel_launch(void* const* d_in, const int* in_sizes, int n_in,
                              void* d_out, int out_size) {
    const float* query = (const float*)d_in[0];
    const float* key   = (const float*)d_in[1];
    const float* value = (const float*)d_in[2];
    const float* bq    = (const float*)d_in[4];
    const float* bk    = (const float*)d_in[6];
    const float* bv    = (const float*)d_in[8];
    const float* pb    = (const float*)d_in[9];
    const float* bo    = (const float*)d_in[11];
    const float* Wq    = (const float*)d_in[3];
    const float* Wk    = (const float*)d_in[5];
    const float* Wv    = (const float*)d_in[7];
    const float* Wo    = (const float*)d_in[10];
    float* out = (float*)d_out;

    float *pq, *pk, *pv;
    __half *phx, *phw, *phy;
    cudaGetSymbolAddress((void**)&pq,  g_q);
    cudaGetSymbolAddress((void**)&pk,  g_k);
    cudaGetSymbolAddress((void**)&pv,  g_v);
    cudaGetSymbolAddress((void**)&phx, g_hx);
    cudaGetSymbolAddress((void**)&phw, g_hw);
    cudaGetSymbolAddress((void**)&phy, g_hy);

    cudaFuncSetAttribute(gemm_qkv, cudaFuncAttributeMaxDynamicSharedMemorySize, GEMM_SMEM);
    cudaFuncSetAttribute(gemm_o,   cudaFuncAttributeMaxDynamicSharedMemorySize, OGEMM_SMEM);

    // 1. fp16 rounding + colmax partials
    prep1_kernel<<<256 + 7168, 256>>>(pb, query, key, value, Wq, Wk, Wv, Wo);
    // 2. epb + colmax final + mlu zero
    prep2_kernel<<<259, 256>>>(pb);

    // 3. q/k/v projections (fp16 operands, fp32 accumulate)
    dim3 ggrid3(M_ROWS / GBM, D_MODEL / GBN, 3);   // (32, 4, 3)
    gemm_qkv<<<ggrid3, 256, GEMM_SMEM>>>(phx, phw, bq, bk, bv, pq, pk, pv);

    // 4. max_logit
    ml_kernel<<<256, 128>>>();

    // 5-7. chunked scans
    scanA_kernel<<<dim3(4, NCHUNK), 256>>>();
    scanB_kernel<<<4, 256>>>();
    scanC_kernel<<<dim3(4, NCHUNK), 256>>>();

    // 8. AFT window + gating (writes fp16 y)
    aft_kernel<<<dim3(64, 16), 256>>>();

    // 9. output projection
    dim3 ogrid(M_ROWS / OBM, D_MODEL / GBN);       // (64, 4)
    gemm_o<<<ogrid, 128, OGEMM_SMEM>>>(phy, phw + 3 * D_MODEL * D_MODEL, bo, out);
}

// round 6
// speedup vs baseline: 2.4187x; 1.2544x over previous
#include <cuda_runtime.h>
#include <cuda_fp16.h>
#include <cstdint>

// ---------------- problem constants ----------------
#define T_LEN   2048
#define BATCH   2
#define D_MODEL 512
#define S_WIN   32
#define M_ROWS  4096           // T*B
#define NCH     1024           // B*D channels

// ---------------- scratch (no allocation allowed) ----------------
__device__ float g_q[M_ROWS * D_MODEL];
__device__ float g_k[M_ROWS * D_MODEL];
__device__ float g_v[M_ROWS * D_MODEL];
__device__ float g_csn[M_ROWS * D_MODEL];
__device__ float g_csd[M_ROWS * D_MODEL];
__device__ float g_ek[M_ROWS * D_MODEL];
__device__ __half g_hx[3 * M_ROWS * D_MODEL];     // fp16 rounded query,key,value
__device__ __half g_hw[4 * D_MODEL * D_MODEL];    // fp16 rounded Wq,Wk,Wv,Wo
__device__ __half g_hy[M_ROWS * D_MODEL];         // fp16 y (gemm_o input)
__device__ float g_epb[T_LEN * S_WIN];

#define NCHUNK 64
#define CHLEN  32              // NCHUNK*CHLEN == T_LEN
__device__ float g_pnum[NCHUNK * NCH];
__device__ float g_pden[NCHUNK * NCH];

// ---------------- helpers ----------------
__device__ __forceinline__ void mma16(float c[4], const uint32_t a[4], const uint32_t b[2]) {
    asm volatile(
        "mma.sync.aligned.m16n8k16.row.col.f32.f16.f16.f32 "
        "{%0,%1,%2,%3}, {%4,%5,%6,%7}, {%8,%9}, {%0,%1,%2,%3};\n"
        : "+f"(c[0]), "+f"(c[1]), "+f"(c[2]), "+f"(c[3])
        : "r"(a[0]), "r"(a[1]), "r"(a[2]), "r"(a[3]),
          "r"(b[0]), "r"(b[1]));
}
__device__ __forceinline__ void ldsm_x4(uint32_t r[4], uint32_t addr) {
    asm volatile("ldmatrix.sync.aligned.m8n8.x4.shared.b16 {%0,%1,%2,%3}, [%4];"
        : "=r"(r[0]), "=r"(r[1]), "=r"(r[2]), "=r"(r[3]) : "r"(addr));
}
__device__ __forceinline__ void cp16(uint32_t dst, const void* src) {
    asm volatile("cp.async.cg.shared.global [%0], [%1], 16;" :: "r"(dst), "l"(src));
}
__device__ __forceinline__ void cp_commit() {
    asm volatile("cp.async.commit_group;" ::: "memory");
}
__device__ __forceinline__ uint32_t smem_to_u32(const void* p) {
    uint32_t a;
    asm("{ .reg .u64 t; cvta.to.shared.u64 t, %1; cvt.u32.u64 %0, t; }" : "=r"(a) : "l"(p));
    return a;
}
__device__ __forceinline__ uint32_t pack_h2(float a, float b) {
    __half2 h = __floats2half2_rn(a, b);
    return *reinterpret_cast<uint32_t*>(&h);
}

// ---------------- prep1: fp16 conversion + exp(pb) window table ----------------
// blocks 0..7167     : convert 1,835,008 float4 -> half4 (q,k,v,Wq,Wk,Wv,Wo)
// blocks 7168..7423  : epb table (65536 entries)
__global__ __launch_bounds__(256) void prep1_kernel(
    const float* __restrict__ pb,
    const float* __restrict__ query, const float* __restrict__ key, const float* __restrict__ value,
    const float* __restrict__ Wq, const float* __restrict__ Wk, const float* __restrict__ Wv,
    const float* __restrict__ Wo)
{
    int blk = blockIdx.x;
    if (blk >= 7168) {
        int id = (blk - 7168) * 256 + threadIdx.x;
        int t = id >> 5, j = id & 31;
        int idx = t - (S_WIN - 1) + j;
        g_epb[id] = (idx >= 0) ? __expf(pb[(size_t)t * T_LEN + idx]) : 0.0f;
        return;
    }
    int i = blk * 256 + threadIdx.x;   // float4 index
    const float4* src;
    __half* dstbase;
    int j;
    if (i < 524288)       { src = (const float4*)query; dstbase = g_hx;           j = i; }
    else if (i < 1048576) { src = (const float4*)key;   dstbase = g_hx + 2097152; j = i - 524288; }
    else if (i < 1572864) { src = (const float4*)value; dstbase = g_hx + 4194304; j = i - 1048576; }
    else if (i < 1638400) { src = (const float4*)Wq;    dstbase = g_hw;           j = i - 1572864; }
    else if (i < 1703936) { src = (const float4*)Wk;    dstbase = g_hw + 262144;  j = i - 1638400; }
    else if (i < 1769472) { src = (const float4*)Wv;    dstbase = g_hw + 524288;  j = i - 1703936; }
    else                  { src = (const float4*)Wo;    dstbase = g_hw + 786432;  j = i - 1769472; }
    float4 v = src[j];
    uint2 h;
    h.x = pack_h2(v.x, v.y);
    h.y = pack_h2(v.z, v.w);
    *reinterpret_cast<uint2*>(dstbase + (size_t)j * 4) = h;
}

// ---------------- fp16 pipelined GEMM (ldmatrix fragments) ----------------
#define GBM 128
#define GBN 128
#define GBK 64
#define GSTG 3
#define NKT 8                       // 512/GBK
#define PADH 72                     // halves per smem row (144 B, conflict-free)
#define ROWB 144                    // bytes per smem row
#define A_HALVES (GBM * PADH)
#define STG_HALVES (2 * A_HALVES)
#define STG_BYTES (STG_HALVES * 2)  // 36,864 B
#define GEMM_SMEM (GSTG * STG_BYTES) // 110,592 B

__device__ __forceinline__ void ld_stage(uint32_t sb, const __half* __restrict__ A,
                                         const __half* __restrict__ W,
                                         int bm, int bn, int kt, int tid) {
    uint32_t base = sb + (uint32_t)((kt % GSTG) * STG_BYTES);
#pragma unroll
    for (int i = 0; i < 4; i++) {
        int chunk = tid + i * 256;             // 1024 chunks: 128 rows x 8x16B
        int row = chunk >> 3, c16 = chunk & 7;
        cp16(base + (uint32_t)(row * ROWB + c16 * 16),
             &A[(size_t)(bm * GBM + row) * 512 + kt * GBK + c16 * 8]);
    }
    base += A_HALVES * 2;
#pragma unroll
    for (int i = 0; i < 4; i++) {
        int chunk = tid + i * 256;
        int row = chunk >> 3, c16 = chunk & 7;
        cp16(base + (uint32_t)(row * ROWB + c16 * 16),
             &W[(size_t)(bn * GBN + row) * 512 + kt * GBK + c16 * 8]);
    }
    cp_commit();
}

__global__ void __launch_bounds__(256, 2) gemm_qkv(
    const __half* __restrict__ X, const __half* __restrict__ Wh,
    const float* __restrict__ B0, const float* __restrict__ B1, const float* __restrict__ B2,
    float* __restrict__ C0, float* __restrict__ C1, float* __restrict__ C2)
{
    extern __shared__ char smem_c[];
    const uint32_t sb = smem_to_u32(smem_c);
    const int tid  = threadIdx.x;
    const int l    = tid & 31;
    const int wid  = tid >> 5;
    const int wm   = wid & 1;        // 2 warps in m
    const int wn   = wid >> 1;       // 4 warps in n
    const int bm   = blockIdx.x, bn = blockIdx.y;
    const int z    = blockIdx.z;

    const __half* A    = X  + (size_t)z * (M_ROWS * D_MODEL);
    const __half* W    = Wh + (size_t)z * (D_MODEL * D_MODEL);
    const float* bias  = (z == 0) ? B0 : (z == 1) ? B1 : B2;
    float*       C     = (z == 0) ? C0 : (z == 1) ? C1 : C2;

    // ldmatrix per-lane address offsets (bytes within tile)
    const uint32_t a_off = (uint32_t)(((l & 7) + ((l >> 3) & 1) * 8) * ROWB + (l >> 4) * 16);
    const uint32_t b_off = (uint32_t)(((l & 7) + (l >> 4) * 8) * ROWB + ((l >> 3) & 1) * 16);

    float acc[4][4][4];
#pragma unroll
    for (int mt = 0; mt < 4; mt++)
#pragma unroll
        for (int nt = 0; nt < 4; nt++)
#pragma unroll
            for (int i = 0; i < 4; i++) acc[mt][nt][i] = 0.0f;

    ld_stage(sb, A, W, bm, bn, 0, tid);
    ld_stage(sb, A, W, bm, bn, 1, tid);

#pragma unroll 1
    for (int kt = 0; kt < NKT; kt++) {
        if (kt < NKT - 2) asm volatile("cp.async.wait_group 1;" ::: "memory");
        else              asm volatile("cp.async.wait_group 0;" ::: "memory");
        __syncthreads();

        if (kt + 2 < NKT) ld_stage(sb, A, W, bm, bn, kt + 2, tid);

        const uint32_t As_u = sb + (uint32_t)((kt % GSTG) * STG_BYTES);
        const uint32_t Bs_u = As_u + A_HALVES * 2;
        const uint32_t a_base = As_u + a_off + (uint32_t)(wm * 64 * ROWB);
        const uint32_t b_base = Bs_u + b_off + (uint32_t)(wn * 32 * ROWB);
#pragma unroll
        for (int ks = 0; ks < 4; ks++) {
            const uint32_t kb = ks * 32;   // 16 halves
            uint32_t a[4][4], b[2][4];
#pragma unroll
            for (int mt = 0; mt < 4; mt++)
                ldsm_x4(a[mt], a_base + (uint32_t)(mt * 16 * ROWB) + kb);
            ldsm_x4(b[0], b_base + kb);
            ldsm_x4(b[1], b_base + (uint32_t)(16 * ROWB) + kb);
#pragma unroll
            for (int mt = 0; mt < 4; mt++)
#pragma unroll
                for (int nt = 0; nt < 4; nt++)
                    mma16(acc[mt][nt], a[mt], &b[nt >> 1][(nt & 1) * 2]);
        }
    }

    const int r_fr = l >> 2;
    const int c2 = (l & 3) * 2;
#pragma unroll
    for (int mt = 0; mt < 4; mt++) {
#pragma unroll
        for (int nt = 0; nt < 4; nt++) {
            int row = bm * GBM + wm * 64 + mt * 16 + r_fr;
            int col = bn * GBN + wn * 32 + nt * 8 + c2;
            float b0 = bias[col], b1 = bias[col + 1];
            *reinterpret_cast<float2*>(&C[(size_t)row * 512 + col]) =
                make_float2(acc[mt][nt][0] + b0, acc[mt][nt][1] + b1);
            *reinterpret_cast<float2*>(&C[(size_t)(row + 8) * 512 + col]) =
                make_float2(acc[mt][nt][2] + b0, acc[mt][nt][3] + b1);
        }
    }
}

// ---------------- BM=64 fp16 GEMM for the output projection ----------------
#define OBM 64
#define OA_HALVES (OBM * PADH)
#define OSTG_HALVES (OA_HALVES + A_HALVES)
#define OSTG_BYTES (OSTG_HALVES * 2)           // 27,648 B
#define OGEMM_SMEM (GSTG * OSTG_BYTES)         // 82,944 B

__device__ __forceinline__ void ld_stage_o(uint32_t sb, const __half* __restrict__ A,
                                           const __half* __restrict__ W,
                                           int bm, int bn, int kt, int tid) {
    uint32_t base = sb + (uint32_t)((kt % GSTG) * OSTG_BYTES);
#pragma unroll
    for (int i = 0; i < 4; i++) {
        int chunk = tid + i * 128;
        int row = chunk >> 3, c16 = chunk & 7;
        cp16(base + (uint32_t)(row * ROWB + c16 * 16),
             &A[(size_t)(bm * OBM + row) * 512 + kt * GBK + c16 * 8]);
    }
    base += OA_HALVES * 2;
#pragma unroll
    for (int i = 0; i < 8; i++) {
        int chunk = tid + i * 128;
        int row = chunk >> 3, c16 = chunk & 7;
        cp16(base + (uint32_t)(row * ROWB + c16 * 16),
             &W[(size_t)(bn * GBN + row) * 512 + kt * GBK + c16 * 8]);
    }
    cp_commit();
}

__global__ void __launch_bounds__(128, 2) gemm_o(
    const __half* __restrict__ A, const __half* __restrict__ W,
    const float* __restrict__ bias, float* __restrict__ C)
{
    extern __shared__ char smem_c[];
    const uint32_t sb = smem_to_u32(smem_c);
    const int tid  = threadIdx.x;
    const int l    = tid & 31;
    const int wn   = tid >> 5;       // 4 warps, all in n
    const int bm   = blockIdx.x, bn = blockIdx.y;

    const uint32_t a_off = (uint32_t)(((l & 7) + ((l >> 3) & 1) * 8) * ROWB + (l >> 4) * 16);
    const uint32_t b_off = (uint32_t)(((l & 7) + (l >> 4) * 8) * ROWB + ((l >> 3) & 1) * 16);

    float acc[4][4][4];
#pragma unroll
    for (int mt = 0; mt < 4; mt++)
#pragma unroll
        for (int nt = 0; nt < 4; nt++)
#pragma unroll
            for (int i = 0; i < 4; i++) acc[mt][nt][i] = 0.0f;

    ld_stage_o(sb, A, W, bm, bn, 0, tid);
    ld_stage_o(sb, A, W, bm, bn, 1, tid);

#pragma unroll 1
    for (int kt = 0; kt < NKT; kt++) {
        if (kt < NKT - 2) asm volatile("cp.async.wait_group 1;" ::: "memory");
        else              asm volatile("cp.async.wait_group 0;" ::: "memory");
        __syncthreads();

        if (kt + 2 < NKT) ld_stage_o(sb, A, W, bm, bn, kt + 2, tid);

        const uint32_t As_u = sb + (uint32_t)((kt % GSTG) * OSTG_BYTES);
        const uint32_t Bs_u = As_u + OA_HALVES * 2;
        const uint32_t a_base = As_u + a_off;
        const uint32_t b_base = Bs_u + b_off + (uint32_t)(wn * 32 * ROWB);
#pragma unroll
        for (int ks = 0; ks < 4; ks++) {
            const uint32_t kb = ks * 32;
            uint32_t a[4][4], b[2][4];
#pragma unroll
            for (int mt = 0; mt < 4; mt++)
                ldsm_x4(a[mt], a_base + (uint32_t)(mt * 16 * ROWB) + kb);
            ldsm_x4(b[0], b_base + kb);
            ldsm_x4(b[1], b_base + (uint32_t)(16 * ROWB) + kb);
#pragma unroll
            for (int mt = 0; mt < 4; mt++)
#pragma unroll
                for (int nt = 0; nt < 4; nt++)
                    mma16(acc[mt][nt], a[mt], &b[nt >> 1][(nt & 1) * 2]);
        }
    }

    const int r_fr = l >> 2;
    const int c2 = (l & 3) * 2;
#pragma unroll
    for (int mt = 0; mt < 4; mt++) {
#pragma unroll
        for (int nt = 0; nt < 4; nt++) {
            int row = bm * OBM + mt * 16 + r_fr;
            int col = bn * GBN + wn * 32 + nt * 8 + c2;
            float b0 = bias[col], b1 = bias[col + 1];
            *reinterpret_cast<float2*>(&C[(size_t)row * 512 + col]) =
                make_float2(acc[mt][nt][0] + b0, acc[mt][nt][1] + b1);
            *reinterpret_cast<float2*>(&C[(size_t)(row + 8) * 512 + col]) =
                make_float2(acc[mt][nt][2] + b0, acc[mt][nt][3] + b1);
        }
    }
}

// ---------------- chunked scan of ek = exp(k), ek*v over T (no max shift) -----------
__global__ void scanA_kernel() {
    int ch = blockIdx.x * 256 + threadIdx.x;
    int t0 = blockIdx.y * CHLEN;
    float sn = 0.f, sd = 0.f;
#pragma unroll 4
    for (int i = 0; i < CHLEN; i++) {
        int t = t0 + i;
        float e = __expf(g_k[(size_t)t * NCH + ch]);
        sd += e;
        sn += e * g_v[(size_t)t * NCH + ch];
    }
    g_pden[blockIdx.y * NCH + ch] = sd;
    g_pnum[blockIdx.y * NCH + ch] = sn;
}

__global__ void scanB_kernel() {
    int ch = blockIdx.x * 256 + threadIdx.x;
    float rd = 0.f, rn = 0.f;
#pragma unroll 4
    for (int c = 0; c < NCHUNK; c++) {
        int i = c * NCH + ch;
        float td = g_pden[i], tn = g_pnum[i];
        g_pden[i] = rd; g_pnum[i] = rn;
        rd += td; rn += tn;
    }
}

__global__ void scanC_kernel() {
    int ch = blockIdx.x * 256 + threadIdx.x;
    int t0 = blockIdx.y * CHLEN;
    float rn = g_pnum[blockIdx.y * NCH + ch];
    float rd = g_pden[blockIdx.y * NCH + ch];
#pragma unroll 4
    for (int i = 0; i < CHLEN; i++) {
        int t = t0 + i;
        float e = __expf(g_k[(size_t)t * NCH + ch]);
        g_ek[(size_t)t * NCH + ch] = e;
        rd += e;
        rn += e * g_v[(size_t)t * NCH + ch];
        g_csd[(size_t)t * NCH + ch] = rd;
        g_csn[(size_t)t * NCH + ch] = rn;
    }
}

// ---------------- AFT local window + gating (FMA-only; y written fp16) --------------
__global__ __launch_bounds__(256) void aft_kernel() {
    __shared__ float2 s_ek[63 * 32];
    __shared__ float2 s_v [63 * 32];
    __shared__ float  s_epb[32 * 32];

    const int tid = threadIdx.x;
    const int w = tid >> 5, l = tid & 31;
    const int t0 = blockIdx.x << 5;
    const int chp = blockIdx.y * 32 + l;

    const float2* ek2 = reinterpret_cast<const float2*>(g_ek);
    const float2* v2g = reinterpret_cast<const float2*>(g_v);

    for (int i = tid; i < 63 * 32; i += 256) {
        int r = i >> 5, cp = i & 31;
        int gr = t0 - 31 + r;
        float2 e = make_float2(0.f, 0.f), vv = make_float2(0.f, 0.f);
        if (gr >= 0) {
            size_t gi = (size_t)gr * 512 + blockIdx.y * 32 + cp;
            e  = ek2[gi];
            vv = v2g[gi];
        }
        s_ek[i] = e; s_v[i] = vv;
    }
    for (int i = tid; i < 1024; i += 256)
        s_epb[i] = g_epb[t0 * 32 + i];
    __syncthreads();

    const float2* csn2 = reinterpret_cast<const float2*>(g_csn);
    const float2* csd2 = reinterpret_cast<const float2*>(g_csd);
    const float2* q2g  = reinterpret_cast<const float2*>(g_q);
    __half2* y2 = reinterpret_cast<__half2*>(g_hy);

#pragma unroll
    for (int ii = 0; ii < 4; ii++) {
        int tl = w + (ii << 3);
        int t  = t0 + tl;
        float nx = 0.f, ny = 0.f, dx = 0.f, dy = 0.f;
        if (t >= S_WIN) {
            float2 n0 = csn2[(size_t)(t - S_WIN) * 512 + chp];
            float2 d0 = csd2[(size_t)(t - S_WIN) * 512 + chp];
            nx = n0.x; ny = n0.y; dx = d0.x; dy = d0.y;
        }
#pragma unroll 8
        for (int j = 0; j < 32; j++) {
            float  ep = s_epb[(tl << 5) + j];
            float2 e2 = s_ek[((tl + j) << 5) + l];
            float2 vv = s_v [((tl + j) << 5) + l];
            float ex = e2.x * ep, ey = e2.y * ep;
            nx += ex * vv.x; ny += ey * vv.y;
            dx += ex;        dy += ey;
        }
        float2 q = q2g[(size_t)t * 512 + chp];
        float sx = 1.f / (1.f + __expf(-q.x));
        float sy = 1.f / (1.f + __expf(-q.y));
        y2[(size_t)t * 512 + chp] = __floats2half2_rn(sx * nx / dx, sy * ny / dy);
    }
}

// ---------------- launch ----------------
extern "C" void kernel_launch(void* const* d_in, const int* in_sizes, int n_in,
                              void* d_out, int out_size) {
    const float* query = (const float*)d_in[0];
    const float* key   = (const float*)d_in[1];
    const float* value = (const float*)d_in[2];
    const float* Wq    = (const float*)d_in[3];
    const float* bq    = (const float*)d_in[4];
    const float* Wk    = (const float*)d_in[5];
    const float* bk    = (const float*)d_in[6];
    const float* Wv    = (const float*)d_in[7];
    const float* bv    = (const float*)d_in[8];
    const float* pb    = (const float*)d_in[9];
    const float* Wo    = (const float*)d_in[10];
    const float* bo    = (const float*)d_in[11];
    float* out = (float*)d_out;

    float *pq, *pk, *pv;
    __half *phx, *phw, *phy;
    cudaGetSymbolAddress((void**)&pq,  g_q);
    cudaGetSymbolAddress((void**)&pk,  g_k);
    cudaGetSymbolAddress((void**)&pv,  g_v);
    cudaGetSymbolAddress((void**)&phx, g_hx);
    cudaGetSymbolAddress((void**)&phw, g_hw);
    cudaGetSymbolAddress((void**)&phy, g_hy);

    cudaFuncSetAttribute(gemm_qkv, cudaFuncAttributeMaxDynamicSharedMemorySize, GEMM_SMEM);
    cudaFuncSetAttribute(gemm_o,   cudaFuncAttributeMaxDynamicSharedMemorySize, OGEMM_SMEM);

    // 1. fp16 rounding + epb table
    prep1_kernel<<<7424, 256>>>(pb, query, key, value, Wq, Wk, Wv, Wo);

    // 2. q/k/v projections (fp16 operands, fp32 accumulate)
    dim3 ggrid3(M_ROWS / GBM, D_MODEL / GBN, 3);   // (32, 4, 3)
    gemm_qkv<<<ggrid3, 256, GEMM_SMEM>>>(phx, phw, bq, bk, bv, pq, pk, pv);

    // 3-5. chunked scans (no max-logit shift: it cancels in num/den)
    scanA_kernel<<<dim3(4, NCHUNK), 256>>>();
    scanB_kernel<<<4, 256>>>();
    scanC_kernel<<<dim3(4, NCHUNK), 256>>>();

    // 6. AFT window + gating (writes fp16 y)
    aft_kernel<<<dim3(64, 16), 256>>>();

    // 7. output projection
    dim3 ogrid(M_ROWS / OBM, D_MODEL / GBN);       // (64, 4)
    gemm_o<<<ogrid, 128, OGEMM_SMEM>>>(phy, phw + 3 * D_MODEL * D_MODEL, bo, out);
}

// round 7
// speedup vs baseline: 2.5753x; 1.0648x over previous
#include <cuda_runtime.h>
#include <cuda_fp16.h>
#include <cstdint>

// ---------------- problem constants ----------------
#define T_LEN   2048
#define BATCH   2
#define D_MODEL 512
#define S_WIN   32
#define M_ROWS  4096           // T*B
#define NCH     1024           // B*D channels

// ---------------- scratch (no allocation allowed) ----------------
__device__ float g_q[M_ROWS * D_MODEL];
__device__ float g_k[M_ROWS * D_MODEL];
__device__ float g_v[M_ROWS * D_MODEL];
__device__ float g_csn[M_ROWS * D_MODEL];
__device__ float g_csd[M_ROWS * D_MODEL];
__device__ float g_ek[M_ROWS * D_MODEL];
__device__ __half g_hx[3 * M_ROWS * D_MODEL];     // fp16 rounded query,key,value
__device__ __half g_hw[4 * D_MODEL * D_MODEL];    // fp16 rounded Wq,Wk,Wv,Wo
__device__ __half g_hy[M_ROWS * D_MODEL];         // fp16 y (gemm_o input)
__device__ float g_epb[T_LEN * S_WIN];

#define NCHUNK 64
#define CHLEN  32              // NCHUNK*CHLEN == T_LEN
// transposed layout: [channel][chunk] so scanB reads contiguously
__device__ float g_pnum[NCH * NCHUNK];
__device__ float g_pden[NCH * NCHUNK];

// ---------------- helpers ----------------
__device__ __forceinline__ void mma16(float c[4], const uint32_t a[4], const uint32_t b[2]) {
    asm volatile(
        "mma.sync.aligned.m16n8k16.row.col.f32.f16.f16.f32 "
        "{%0,%1,%2,%3}, {%4,%5,%6,%7}, {%8,%9}, {%0,%1,%2,%3};\n"
        : "+f"(c[0]), "+f"(c[1]), "+f"(c[2]), "+f"(c[3])
        : "r"(a[0]), "r"(a[1]), "r"(a[2]), "r"(a[3]),
          "r"(b[0]), "r"(b[1]));
}
__device__ __forceinline__ void ldsm_x4(uint32_t r[4], uint32_t addr) {
    asm volatile("ldmatrix.sync.aligned.m8n8.x4.shared.b16 {%0,%1,%2,%3}, [%4];"
        : "=r"(r[0]), "=r"(r[1]), "=r"(r[2]), "=r"(r[3]) : "r"(addr));
}
__device__ __forceinline__ void cp16(uint32_t dst, const void* src) {
    asm volatile("cp.async.cg.shared.global [%0], [%1], 16;" :: "r"(dst), "l"(src));
}
__device__ __forceinline__ void cp_commit() {
    asm volatile("cp.async.commit_group;" ::: "memory");
}
__device__ __forceinline__ uint32_t smem_to_u32(const void* p) {
    uint32_t a;
    asm("{ .reg .u64 t; cvta.to.shared.u64 t, %1; cvt.u32.u64 %0, t; }" : "=r"(a) : "l"(p));
    return a;
}
__device__ __forceinline__ uint32_t pack_h2(float a, float b) {
    __half2 h = __floats2half2_rn(a, b);
    return *reinterpret_cast<uint32_t*>(&h);
}

// ---------------- prep1: fp16 conversion + exp(pb) window table ----------------
__global__ __launch_bounds__(256) void prep1_kernel(
    const float* __restrict__ pb,
    const float* __restrict__ query, const float* __restrict__ key, const float* __restrict__ value,
    const float* __restrict__ Wq, const float* __restrict__ Wk, const float* __restrict__ Wv,
    const float* __restrict__ Wo)
{
    int blk = blockIdx.x;
    if (blk >= 7168) {
        int id = (blk - 7168) * 256 + threadIdx.x;
        int t = id >> 5, j = id & 31;
        int idx = t - (S_WIN - 1) + j;
        g_epb[id] = (idx >= 0) ? __expf(pb[(size_t)t * T_LEN + idx]) : 0.0f;
        return;
    }
    int i = blk * 256 + threadIdx.x;   // float4 index
    const float4* src;
    __half* dstbase;
    int j;
    if (i < 524288)       { src = (const float4*)query; dstbase = g_hx;           j = i; }
    else if (i < 1048576) { src = (const float4*)key;   dstbase = g_hx + 2097152; j = i - 524288; }
    else if (i < 1572864) { src = (const float4*)value; dstbase = g_hx + 4194304; j = i - 1048576; }
    else if (i < 1638400) { src = (const float4*)Wq;    dstbase = g_hw;           j = i - 1572864; }
    else if (i < 1703936) { src = (const float4*)Wk;    dstbase = g_hw + 262144;  j = i - 1638400; }
    else if (i < 1769472) { src = (const float4*)Wv;    dstbase = g_hw + 524288;  j = i - 1703936; }
    else                  { src = (const float4*)Wo;    dstbase = g_hw + 786432;  j = i - 1769472; }
    float4 v = src[j];
    uint2 h;
    h.x = pack_h2(v.x, v.y);
    h.y = pack_h2(v.z, v.w);
    *reinterpret_cast<uint2*>(dstbase + (size_t)j * 4) = h;
}

// ---------------- fp16 pipelined GEMM (ldmatrix fragments) ----------------
#define GBM 128
#define GBN 128
#define GBK 64
#define GSTG 3
#define NKT 8                       // 512/GBK
#define PADH 72                     // halves per smem row (144 B, conflict-free)
#define ROWB 144                    // bytes per smem row
#define A_HALVES (GBM * PADH)
#define STG_HALVES (2 * A_HALVES)
#define STG_BYTES (STG_HALVES * 2)  // 36,864 B
#define GEMM_SMEM (GSTG * STG_BYTES) // 110,592 B

__device__ __forceinline__ void ld_stage(uint32_t sb, const __half* __restrict__ A,
                                         const __half* __restrict__ W,
                                         int bm, int bn, int kt, int tid) {
    uint32_t base = sb + (uint32_t)((kt % GSTG) * STG_BYTES);
#pragma unroll
    for (int i = 0; i < 4; i++) {
        int chunk = tid + i * 256;
        int row = chunk >> 3, c16 = chunk & 7;
        cp16(base + (uint32_t)(row * ROWB + c16 * 16),
             &A[(size_t)(bm * GBM + row) * 512 + kt * GBK + c16 * 8]);
    }
    base += A_HALVES * 2;
#pragma unroll
    for (int i = 0; i < 4; i++) {
        int chunk = tid + i * 256;
        int row = chunk >> 3, c16 = chunk & 7;
        cp16(base + (uint32_t)(row * ROWB + c16 * 16),
             &W[(size_t)(bn * GBN + row) * 512 + kt * GBK + c16 * 8]);
    }
    cp_commit();
}

__global__ void __launch_bounds__(256, 2) gemm_qkv(
    const __half* __restrict__ X, const __half* __restrict__ Wh,
    const float* __restrict__ B0, const float* __restrict__ B1, const float* __restrict__ B2,
    float* __restrict__ C0, float* __restrict__ C1, float* __restrict__ C2)
{
    extern __shared__ char smem_c[];
    const uint32_t sb = smem_to_u32(smem_c);
    const int tid  = threadIdx.x;
    const int l    = tid & 31;
    const int wid  = tid >> 5;
    const int wm   = wid & 1;
    const int wn   = wid >> 1;
    const int bm   = blockIdx.x, bn = blockIdx.y;
    const int z    = blockIdx.z;

    const __half* A    = X  + (size_t)z * (M_ROWS * D_MODEL);
    const __half* W    = Wh + (size_t)z * (D_MODEL * D_MODEL);
    const float* bias  = (z == 0) ? B0 : (z == 1) ? B1 : B2;
    float*       C     = (z == 0) ? C0 : (z == 1) ? C1 : C2;

    const uint32_t a_off = (uint32_t)(((l & 7) + ((l >> 3) & 1) * 8) * ROWB + (l >> 4) * 16);
    const uint32_t b_off = (uint32_t)(((l & 7) + (l >> 4) * 8) * ROWB + ((l >> 3) & 1) * 16);

    float acc[4][4][4];
#pragma unroll
    for (int mt = 0; mt < 4; mt++)
#pragma unroll
        for (int nt = 0; nt < 4; nt++)
#pragma unroll
            for (int i = 0; i < 4; i++) acc[mt][nt][i] = 0.0f;

    ld_stage(sb, A, W, bm, bn, 0, tid);
    ld_stage(sb, A, W, bm, bn, 1, tid);

#pragma unroll 1
    for (int kt = 0; kt < NKT; kt++) {
        if (kt < NKT - 2) asm volatile("cp.async.wait_group 1;" ::: "memory");
        else              asm volatile("cp.async.wait_group 0;" ::: "memory");
        __syncthreads();

        if (kt + 2 < NKT) ld_stage(sb, A, W, bm, bn, kt + 2, tid);

        const uint32_t As_u = sb + (uint32_t)((kt % GSTG) * STG_BYTES);
        const uint32_t Bs_u = As_u + A_HALVES * 2;
        const uint32_t a_base = As_u + a_off + (uint32_t)(wm * 64 * ROWB);
        const uint32_t b_base = Bs_u + b_off + (uint32_t)(wn * 32 * ROWB);
#pragma unroll
        for (int ks = 0; ks < 4; ks++) {
            const uint32_t kb = ks * 32;
            uint32_t a[4][4], b[2][4];
#pragma unroll
            for (int mt = 0; mt < 4; mt++)
                ldsm_x4(a[mt], a_base + (uint32_t)(mt * 16 * ROWB) + kb);
            ldsm_x4(b[0], b_base + kb);
            ldsm_x4(b[1], b_base + (uint32_t)(16 * ROWB) + kb);
#pragma unroll
            for (int mt = 0; mt < 4; mt++)
#pragma unroll
                for (int nt = 0; nt < 4; nt++)
                    mma16(acc[mt][nt], a[mt], &b[nt >> 1][(nt & 1) * 2]);
        }
    }

    const int r_fr = l >> 2;
    const int c2 = (l & 3) * 2;
#pragma unroll
    for (int mt = 0; mt < 4; mt++) {
#pragma unroll
        for (int nt = 0; nt < 4; nt++) {
            int row = bm * GBM + wm * 64 + mt * 16 + r_fr;
            int col = bn * GBN + wn * 32 + nt * 8 + c2;
            float b0 = bias[col], b1 = bias[col + 1];
            *reinterpret_cast<float2*>(&C[(size_t)row * 512 + col]) =
                make_float2(acc[mt][nt][0] + b0, acc[mt][nt][1] + b1);
            *reinterpret_cast<float2*>(&C[(size_t)(row + 8) * 512 + col]) =
                make_float2(acc[mt][nt][2] + b0, acc[mt][nt][3] + b1);
        }
    }
}

// ---------------- BM=64 fp16 GEMM for the output projection ----------------
#define OBM 64
#define OA_HALVES (OBM * PADH)
#define OSTG_HALVES (OA_HALVES + A_HALVES)
#define OSTG_BYTES (OSTG_HALVES * 2)           // 27,648 B
#define OGEMM_SMEM (GSTG * OSTG_BYTES)         // 82,944 B

__device__ __forceinline__ void ld_stage_o(uint32_t sb, const __half* __restrict__ A,
                                           const __half* __restrict__ W,
                                           int bm, int bn, int kt, int tid) {
    uint32_t base = sb + (uint32_t)((kt % GSTG) * OSTG_BYTES);
#pragma unroll
    for (int i = 0; i < 4; i++) {
        int chunk = tid + i * 128;
        int row = chunk >> 3, c16 = chunk & 7;
        cp16(base + (uint32_t)(row * ROWB + c16 * 16),
             &A[(size_t)(bm * OBM + row) * 512 + kt * GBK + c16 * 8]);
    }
    base += OA_HALVES * 2;
#pragma unroll
    for (int i = 0; i < 8; i++) {
        int chunk = tid + i * 128;
        int row = chunk >> 3, c16 = chunk & 7;
        cp16(base + (uint32_t)(row * ROWB + c16 * 16),
             &W[(size_t)(bn * GBN + row) * 512 + kt * GBK + c16 * 8]);
    }
    cp_commit();
}

__global__ void __launch_bounds__(128, 2) gemm_o(
    const __half* __restrict__ A, const __half* __restrict__ W,
    const float* __restrict__ bias, float* __restrict__ C)
{
    extern __shared__ char smem_c[];
    const uint32_t sb = smem_to_u32(smem_c);
    const int tid  = threadIdx.x;
    const int l    = tid & 31;
    const int wn   = tid >> 5;
    const int bm   = blockIdx.x, bn = blockIdx.y;

    const uint32_t a_off = (uint32_t)(((l & 7) + ((l >> 3) & 1) * 8) * ROWB + (l >> 4) * 16);
    const uint32_t b_off = (uint32_t)(((l & 7) + (l >> 4) * 8) * ROWB + ((l >> 3) & 1) * 16);

    float acc[4][4][4];
#pragma unroll
    for (int mt = 0; mt < 4; mt++)
#pragma unroll
        for (int nt = 0; nt < 4; nt++)
#pragma unroll
            for (int i = 0; i < 4; i++) acc[mt][nt][i] = 0.0f;

    ld_stage_o(sb, A, W, bm, bn, 0, tid);
    ld_stage_o(sb, A, W, bm, bn, 1, tid);

#pragma unroll 1
    for (int kt = 0; kt < NKT; kt++) {
        if (kt < NKT - 2) asm volatile("cp.async.wait_group 1;" ::: "memory");
        else              asm volatile("cp.async.wait_group 0;" ::: "memory");
        __syncthreads();

        if (kt + 2 < NKT) ld_stage_o(sb, A, W, bm, bn, kt + 2, tid);

        const uint32_t As_u = sb + (uint32_t)((kt % GSTG) * OSTG_BYTES);
        const uint32_t Bs_u = As_u + OA_HALVES * 2;
        const uint32_t a_base = As_u + a_off;
        const uint32_t b_base = Bs_u + b_off + (uint32_t)(wn * 32 * ROWB);
#pragma unroll
        for (int ks = 0; ks < 4; ks++) {
            const uint32_t kb = ks * 32;
            uint32_t a[4][4], b[2][4];
#pragma unroll
            for (int mt = 0; mt < 4; mt++)
                ldsm_x4(a[mt], a_base + (uint32_t)(mt * 16 * ROWB) + kb);
            ldsm_x4(b[0], b_base + kb);
            ldsm_x4(b[1], b_base + (uint32_t)(16 * ROWB) + kb);
#pragma unroll
            for (int mt = 0; mt < 4; mt++)
#pragma unroll
                for (int nt = 0; nt < 4; nt++)
                    mma16(acc[mt][nt], a[mt], &b[nt >> 1][(nt & 1) * 2]);
        }
    }

    const int r_fr = l >> 2;
    const int c2 = (l & 3) * 2;
#pragma unroll
    for (int mt = 0; mt < 4; mt++) {
#pragma unroll
        for (int nt = 0; nt < 4; nt++) {
            int row = bm * OBM + mt * 16 + r_fr;
            int col = bn * GBN + wn * 32 + nt * 8 + c2;
            float b0 = bias[col], b1 = bias[col + 1];
            *reinterpret_cast<float2*>(&C[(size_t)row * 512 + col]) =
                make_float2(acc[mt][nt][0] + b0, acc[mt][nt][1] + b1);
            *reinterpret_cast<float2*>(&C[(size_t)(row + 8) * 512 + col]) =
                make_float2(acc[mt][nt][2] + b0, acc[mt][nt][3] + b1);
        }
    }
}

// ---------------- chunked scan of ek = exp(k), ek*v over T ----------------
__global__ void scanA_kernel() {
    int ch = blockIdx.x * 256 + threadIdx.x;
    int t0 = blockIdx.y * CHLEN;
    float sn = 0.f, sd = 0.f;
#pragma unroll 4
    for (int i = 0; i < CHLEN; i++) {
        int t = t0 + i;
        float e = __expf(g_k[(size_t)t * NCH + ch]);
        sd += e;
        sn += e * g_v[(size_t)t * NCH + ch];
    }
    g_pden[ch * NCHUNK + blockIdx.y] = sd;     // transposed [ch][chunk]
    g_pnum[ch * NCHUNK + blockIdx.y] = sn;
}

// per-thread contiguous float4 prefix over 64 chunks (MLP-friendly)
__global__ void scanB_kernel() {
    int ch = blockIdx.x * 256 + threadIdx.x;   // 4 blocks
    float4* pn4 = reinterpret_cast<float4*>(g_pnum + ch * NCHUNK);
    float4* pd4 = reinterpret_cast<float4*>(g_pden + ch * NCHUNK);
    float rn = 0.f, rd = 0.f;
#pragma unroll 4
    for (int c = 0; c < NCHUNK / 4; c++) {
        float4 tn = pn4[c], td = pd4[c];
        float4 on, od;
        on.x = rn; od.x = rd; rn += tn.x; rd += td.x;
        on.y = rn; od.y = rd; rn += tn.y; rd += td.y;
        on.z = rn; od.z = rd; rn += tn.z; rd += td.z;
        on.w = rn; od.w = rd; rn += tn.w; rd += td.w;
        pn4[c] = on; pd4[c] = od;              // exclusive offsets
    }
}

__global__ void scanC_kernel() {
    int ch = blockIdx.x * 256 + threadIdx.x;
    int t0 = blockIdx.y * CHLEN;
    float rn = g_pnum[ch * NCHUNK + blockIdx.y];
    float rd = g_pden[ch * NCHUNK + blockIdx.y];
#pragma unroll 4
    for (int i = 0; i < CHLEN; i++) {
        int t = t0 + i;
        float e = __expf(g_k[(size_t)t * NCH + ch]);
        g_ek[(size_t)t * NCH + ch] = e;
        rd += e;
        rn += e * g_v[(size_t)t * NCH + ch];
        g_csd[(size_t)t * NCH + ch] = rd;
        g_csn[(size_t)t * NCH + ch] = rn;
    }
}

// ---------------- AFT local window + gating (row-sliding, fewer LDS) ----------------
// Block: 32 t-values x 64 channels (float2/thread). Each thread owns 4 t-values
// (tl = w + 8*ii) and slides over the 56 halo rows it touches, scattering each
// row into the t-accumulators whose window contains it. ii-sets constant per
// 8-row group -> fully unrolled, branch-free.
__global__ __launch_bounds__(256) void aft_kernel() {
    __shared__ float2 s_ek[63 * 32];
    __shared__ float2 s_v [63 * 32];
    __shared__ float  s_epb[32 * 32];

    const int tid = threadIdx.x;
    const int w = tid >> 5, l = tid & 31;
    const int t0 = blockIdx.x << 5;
    const int chp = blockIdx.y * 32 + l;

    const float2* ek2 = reinterpret_cast<const float2*>(g_ek);
    const float2* v2g = reinterpret_cast<const float2*>(g_v);

    for (int i = tid; i < 63 * 32; i += 256) {
        int r = i >> 5, cp = i & 31;
        int gr = t0 - 31 + r;
        float2 e = make_float2(0.f, 0.f), vv = make_float2(0.f, 0.f);
        if (gr >= 0) {
            size_t gi = (size_t)gr * 512 + blockIdx.y * 32 + cp;
            e  = ek2[gi];
            vv = v2g[gi];
        }
        s_ek[i] = e; s_v[i] = vv;
    }
    for (int i = tid; i < 1024; i += 256)
        s_epb[i] = g_epb[t0 * 32 + i];
    __syncthreads();

    const float2* csn2 = reinterpret_cast<const float2*>(g_csn);
    const float2* csd2 = reinterpret_cast<const float2*>(g_csd);
    const float2* q2g  = reinterpret_cast<const float2*>(g_q);
    __half2* y2 = reinterpret_cast<__half2*>(g_hy);

    float acc[4][4];     // [ii][nx, ny, dx, dy]
#pragma unroll
    for (int ii = 0; ii < 4; ii++) {
        int t = t0 + w + (ii << 3);
        if (t >= S_WIN) {
            float2 n0 = csn2[(size_t)(t - S_WIN) * 512 + chp];
            float2 d0 = csd2[(size_t)(t - S_WIN) * 512 + chp];
            acc[ii][0] = n0.x; acc[ii][1] = n0.y;
            acc[ii][2] = d0.x; acc[ii][3] = d0.y;
        } else {
            acc[ii][0] = acc[ii][1] = acc[ii][2] = acc[ii][3] = 0.f;
        }
    }

    // row groups: rows r in [8g, 8g+7], valid ii in [lo[g], hi[g]]
    const int ii_lo[7] = {0, 0, 0, 0, 1, 2, 3};
    const int ii_hi[7] = {0, 1, 2, 3, 3, 3, 3};
#pragma unroll
    for (int g = 0; g < 7; g++) {
#pragma unroll
        for (int rr = 0; rr < 8; rr++) {
            const int r = g * 8 + rr;          // 0..55
            const int row = w + r;             // 0..62
            float2 e2 = s_ek[(row << 5) + l];
            float2 vv = s_v [(row << 5) + l];
#pragma unroll
            for (int ii = ii_lo[g]; ii <= ii_hi[g]; ii++) {
                const int tl = w + (ii << 3);
                const int j  = r - (ii << 3);  // 0..31
                float ep = s_epb[(tl << 5) + j];       // warp-uniform broadcast
                float ex = e2.x * ep, ey = e2.y * ep;
                acc[ii][0] += ex * vv.x; acc[ii][1] += ey * vv.y;
                acc[ii][2] += ex;        acc[ii][3] += ey;
            }
        }
    }

#pragma unroll
    for (int ii = 0; ii < 4; ii++) {
        int t = t0 + w + (ii << 3);
        float2 q = q2g[(size_t)t * 512 + chp];
        float sx = 1.f / (1.f + __expf(-q.x));
        float sy = 1.f / (1.f + __expf(-q.y));
        y2[(size_t)t * 512 + chp] =
            __floats2half2_rn(sx * acc[ii][0] / acc[ii][2], sy * acc[ii][1] / acc[ii][3]);
    }
}

// ---------------- launch ----------------
extern "C" void kernel_launch(void* const* d_in, const int* in_sizes, int n_in,
                              void* d_out, int out_size) {
    const float* query = (const float*)d_in[0];
    const float* key   = (const float*)d_in[1];
    const float* value = (const float*)d_in[2];
    const float* Wq    = (const float*)d_in[3];
    const float* bq    = (const float*)d_in[4];
    const float* Wk    = (const float*)d_in[5];
    const float* bk    = (const float*)d_in[6];
    const float* Wv    = (const float*)d_in[7];
    const float* bv    = (const float*)d_in[8];
    const float* pb    = (const float*)d_in[9];
    const float* Wo    = (const float*)d_in[10];
    const float* bo    = (const float*)d_in[11];
    float* out = (float*)d_out;

    float *pq, *pk, *pv;
    __half *phx, *phw, *phy;
    cudaGetSymbolAddress((void**)&pq,  g_q);
    cudaGetSymbolAddress((void**)&pk,  g_k);
    cudaGetSymbolAddress((void**)&pv,  g_v);
    cudaGetSymbolAddress((void**)&phx, g_hx);
    cudaGetSymbolAddress((void**)&phw, g_hw);
    cudaGetSymbolAddress((void**)&phy, g_hy);

    cudaFuncSetAttribute(gemm_qkv, cudaFuncAttributeMaxDynamicSharedMemorySize, GEMM_SMEM);
    cudaFuncSetAttribute(gemm_o,   cudaFuncAttributeMaxDynamicSharedMemorySize, OGEMM_SMEM);

    // 1. fp16 rounding + epb table
    prep1_kernel<<<7424, 256>>>(pb, query, key, value, Wq, Wk, Wv, Wo);

    // 2. q/k/v projections
    dim3 ggrid3(M_ROWS / GBM, D_MODEL / GBN, 3);   // (32, 4, 3)
    gemm_qkv<<<ggrid3, 256, GEMM_SMEM>>>(phx, phw, bq, bk, bv, pq, pk, pv);

    // 3-5. chunked scans (transposed partials)
    scanA_kernel<<<dim3(4, NCHUNK), 256>>>();
    scanB_kernel<<<4, 256>>>();
    scanC_kernel<<<dim3(4, NCHUNK), 256>>>();

    // 6. AFT window + gating (writes fp16 y)
    aft_kernel<<<dim3(64, 16), 256>>>();

    // 7. output projection
    dim3 ogrid(M_ROWS / OBM, D_MODEL / GBN);       // (64, 4)
    gemm_o<<<ogrid, 128, OGEMM_SMEM>>>(phy, phw + 3 * D_MODEL * D_MODEL, bo, out);
}

// round 8
// speedup vs baseline: 2.9596x; 1.1492x over previous
#include <cuda_runtime.h>
#include <cuda_fp16.h>
#include <cstdint>

// ---------------- problem constants ----------------
#define T_LEN   2048
#define BATCH   2
#define D_MODEL 512
#define S_WIN   32
#define M_ROWS  4096           // T*B
#define NCH     1024           // B*D channels

// ---------------- scratch (no allocation allowed) ----------------
__device__ float g_q[M_ROWS * D_MODEL];
__device__ float g_k[M_ROWS * D_MODEL];
__device__ float g_v[M_ROWS * D_MODEL];
__device__ float g_ek[M_ROWS * D_MODEL];
__device__ __half g_hx[3 * M_ROWS * D_MODEL];     // fp16 rounded query,key,value
__device__ __half g_hw[4 * D_MODEL * D_MODEL];    // fp16 rounded Wq,Wk,Wv,Wo
__device__ __half g_hy[M_ROWS * D_MODEL];         // fp16 y (gemm_o input)
__device__ float g_epb[T_LEN * S_WIN];

#define NCHUNK 64
#define CHLEN  32              // == S_WIN (prefix-in-block trick relies on this)
// [channel][chunk], becomes EXCLUSIVE chunk prefix after scanB
__device__ float g_pnum[NCH * NCHUNK];
__device__ float g_pden[NCH * NCHUNK];

// ---------------- helpers ----------------
__device__ __forceinline__ void mma16(float c[4], const uint32_t a[4], const uint32_t b[2]) {
    asm volatile(
        "mma.sync.aligned.m16n8k16.row.col.f32.f16.f16.f32 "
        "{%0,%1,%2,%3}, {%4,%5,%6,%7}, {%8,%9}, {%0,%1,%2,%3};\n"
        : "+f"(c[0]), "+f"(c[1]), "+f"(c[2]), "+f"(c[3])
        : "r"(a[0]), "r"(a[1]), "r"(a[2]), "r"(a[3]),
          "r"(b[0]), "r"(b[1]));
}
__device__ __forceinline__ void ldsm_x4(uint32_t r[4], uint32_t addr) {
    asm volatile("ldmatrix.sync.aligned.m8n8.x4.shared.b16 {%0,%1,%2,%3}, [%4];"
        : "=r"(r[0]), "=r"(r[1]), "=r"(r[2]), "=r"(r[3]) : "r"(addr));
}
__device__ __forceinline__ void cp16(uint32_t dst, const void* src) {
    asm volatile("cp.async.cg.shared.global [%0], [%1], 16;" :: "r"(dst), "l"(src));
}
__device__ __forceinline__ void cp_commit() {
    asm volatile("cp.async.commit_group;" ::: "memory");
}
__device__ __forceinline__ uint32_t smem_to_u32(const void* p) {
    uint32_t a;
    asm("{ .reg .u64 t; cvta.to.shared.u64 t, %1; cvt.u32.u64 %0, t; }" : "=r"(a) : "l"(p));
    return a;
}
__device__ __forceinline__ uint32_t pack_h2(float a, float b) {
    __half2 h = __floats2half2_rn(a, b);
    return *reinterpret_cast<uint32_t*>(&h);
}

// ---------------- prep1: fp16 conversion + exp(pb) window table ----------------
__global__ __launch_bounds__(256) void prep1_kernel(
    const float* __restrict__ pb,
    const float* __restrict__ query, const float* __restrict__ key, const float* __restrict__ value,
    const float* __restrict__ Wq, const float* __restrict__ Wk, const float* __restrict__ Wv,
    const float* __restrict__ Wo)
{
    int blk = blockIdx.x;
    if (blk >= 7168) {
        int id = (blk - 7168) * 256 + threadIdx.x;
        int t = id >> 5, j = id & 31;
        int idx = t - (S_WIN - 1) + j;
        g_epb[id] = (idx >= 0) ? __expf(pb[(size_t)t * T_LEN + idx]) : 0.0f;
        return;
    }
    int i = blk * 256 + threadIdx.x;   // float4 index
    const float4* src;
    __half* dstbase;
    int j;
    if (i < 524288)       { src = (const float4*)query; dstbase = g_hx;           j = i; }
    else if (i < 1048576) { src = (const float4*)key;   dstbase = g_hx + 2097152; j = i - 524288; }
    else if (i < 1572864) { src = (const float4*)value; dstbase = g_hx + 4194304; j = i - 1048576; }
    else if (i < 1638400) { src = (const float4*)Wq;    dstbase = g_hw;           j = i - 1572864; }
    else if (i < 1703936) { src = (const float4*)Wk;    dstbase = g_hw + 262144;  j = i - 1638400; }
    else if (i < 1769472) { src = (const float4*)Wv;    dstbase = g_hw + 524288;  j = i - 1703936; }
    else                  { src = (const float4*)Wo;    dstbase = g_hw + 786432;  j = i - 1769472; }
    float4 v = src[j];
    uint2 h;
    h.x = pack_h2(v.x, v.y);
    h.y = pack_h2(v.z, v.w);
    *reinterpret_cast<uint2*>(dstbase + (size_t)j * 4) = h;
}

// ---------------- fp16 pipelined GEMM (ldmatrix fragments) ----------------
#define GBM 128
#define GBN 128
#define GBK 64
#define GSTG 3
#define NKT 8
#define PADH 72
#define ROWB 144
#define A_HALVES (GBM * PADH)
#define STG_HALVES (2 * A_HALVES)
#define STG_BYTES (STG_HALVES * 2)
#define GEMM_SMEM (GSTG * STG_BYTES)

__device__ __forceinline__ void ld_stage(uint32_t sb, const __half* __restrict__ A,
                                         const __half* __restrict__ W,
                                         int bm, int bn, int kt, int tid) {
    uint32_t base = sb + (uint32_t)((kt % GSTG) * STG_BYTES);
#pragma unroll
    for (int i = 0; i < 4; i++) {
        int chunk = tid + i * 256;
        int row = chunk >> 3, c16 = chunk & 7;
        cp16(base + (uint32_t)(row * ROWB + c16 * 16),
             &A[(size_t)(bm * GBM + row) * 512 + kt * GBK + c16 * 8]);
    }
    base += A_HALVES * 2;
#pragma unroll
    for (int i = 0; i < 4; i++) {
        int chunk = tid + i * 256;
        int row = chunk >> 3, c16 = chunk & 7;
        cp16(base + (uint32_t)(row * ROWB + c16 * 16),
             &W[(size_t)(bn * GBN + row) * 512 + kt * GBK + c16 * 8]);
    }
    cp_commit();
}

__global__ void __launch_bounds__(256, 2) gemm_qkv(
    const __half* __restrict__ X, const __half* __restrict__ Wh,
    const float* __restrict__ B0, const float* __restrict__ B1, const float* __restrict__ B2,
    float* __restrict__ C0, float* __restrict__ C1, float* __restrict__ C2)
{
    extern __shared__ char smem_c[];
    const uint32_t sb = smem_to_u32(smem_c);
    const int tid  = threadIdx.x;
    const int l    = tid & 31;
    const int wid  = tid >> 5;
    const int wm   = wid & 1;
    const int wn   = wid >> 1;
    const int bm   = blockIdx.x, bn = blockIdx.y;
    const int z    = blockIdx.z;

    const __half* A    = X  + (size_t)z * (M_ROWS * D_MODEL);
    const __half* W    = Wh + (size_t)z * (D_MODEL * D_MODEL);
    const float* bias  = (z == 0) ? B0 : (z == 1) ? B1 : B2;
    float*       C     = (z == 0) ? C0 : (z == 1) ? C1 : C2;

    const uint32_t a_off = (uint32_t)(((l & 7) + ((l >> 3) & 1) * 8) * ROWB + (l >> 4) * 16);
    const uint32_t b_off = (uint32_t)(((l & 7) + (l >> 4) * 8) * ROWB + ((l >> 3) & 1) * 16);

    float acc[4][4][4];
#pragma unroll
    for (int mt = 0; mt < 4; mt++)
#pragma unroll
        for (int nt = 0; nt < 4; nt++)
#pragma unroll
            for (int i = 0; i < 4; i++) acc[mt][nt][i] = 0.0f;

    ld_stage(sb, A, W, bm, bn, 0, tid);
    ld_stage(sb, A, W, bm, bn, 1, tid);

#pragma unroll 1
    for (int kt = 0; kt < NKT; kt++) {
        if (kt < NKT - 2) asm volatile("cp.async.wait_group 1;" ::: "memory");
        else              asm volatile("cp.async.wait_group 0;" ::: "memory");
        __syncthreads();

        if (kt + 2 < NKT) ld_stage(sb, A, W, bm, bn, kt + 2, tid);

        const uint32_t As_u = sb + (uint32_t)((kt % GSTG) * STG_BYTES);
        const uint32_t Bs_u = As_u + A_HALVES * 2;
        const uint32_t a_base = As_u + a_off + (uint32_t)(wm * 64 * ROWB);
        const uint32_t b_base = Bs_u + b_off + (uint32_t)(wn * 32 * ROWB);
#pragma unroll
        for (int ks = 0; ks < 4; ks++) {
            const uint32_t kb = ks * 32;
            uint32_t a[4][4], b[2][4];
#pragma unroll
            for (int mt = 0; mt < 4; mt++)
                ldsm_x4(a[mt], a_base + (uint32_t)(mt * 16 * ROWB) + kb);
            ldsm_x4(b[0], b_base + kb);
            ldsm_x4(b[1], b_base + (uint32_t)(16 * ROWB) + kb);
#pragma unroll
            for (int mt = 0; mt < 4; mt++)
#pragma unroll
                for (int nt = 0; nt < 4; nt++)
                    mma16(acc[mt][nt], a[mt], &b[nt >> 1][(nt & 1) * 2]);
        }
    }

    const int r_fr = l >> 2;
    const int c2 = (l & 3) * 2;
#pragma unroll
    for (int mt = 0; mt < 4; mt++) {
#pragma unroll
        for (int nt = 0; nt < 4; nt++) {
            int row = bm * GBM + wm * 64 + mt * 16 + r_fr;
            int col = bn * GBN + wn * 32 + nt * 8 + c2;
            float b0 = bias[col], b1 = bias[col + 1];
            *reinterpret_cast<float2*>(&C[(size_t)row * 512 + col]) =
                make_float2(acc[mt][nt][0] + b0, acc[mt][nt][1] + b1);
            *reinterpret_cast<float2*>(&C[(size_t)(row + 8) * 512 + col]) =
                make_float2(acc[mt][nt][2] + b0, acc[mt][nt][3] + b1);
        }
    }
}

// ---------------- BM=64 fp16 GEMM for the output projection ----------------
#define OBM 64
#define OA_HALVES (OBM * PADH)
#define OSTG_HALVES (OA_HALVES + A_HALVES)
#define OSTG_BYTES (OSTG_HALVES * 2)
#define OGEMM_SMEM (GSTG * OSTG_BYTES)

__device__ __forceinline__ void ld_stage_o(uint32_t sb, const __half* __restrict__ A,
                                           const __half* __restrict__ W,
                                           int bm, int bn, int kt, int tid) {
    uint32_t base = sb + (uint32_t)((kt % GSTG) * OSTG_BYTES);
#pragma unroll
    for (int i = 0; i < 4; i++) {
        int chunk = tid + i * 128;
        int row = chunk >> 3, c16 = chunk & 7;
        cp16(base + (uint32_t)(row * ROWB + c16 * 16),
             &A[(size_t)(bm * OBM + row) * 512 + kt * GBK + c16 * 8]);
    }
    base += OA_HALVES * 2;
#pragma unroll
    for (int i = 0; i < 8; i++) {
        int chunk = tid + i * 128;
        int row = chunk >> 3, c16 = chunk & 7;
        cp16(base + (uint32_t)(row * ROWB + c16 * 16),
             &W[(size_t)(bn * GBN + row) * 512 + kt * GBK + c16 * 8]);
    }
    cp_commit();
}

__global__ void __launch_bounds__(128, 2) gemm_o(
    const __half* __restrict__ A, const __half* __restrict__ W,
    const float* __restrict__ bias, float* __restrict__ C)
{
    extern __shared__ char smem_c[];
    const uint32_t sb = smem_to_u32(smem_c);
    const int tid  = threadIdx.x;
    const int l    = tid & 31;
    const int wn   = tid >> 5;
    const int bm   = blockIdx.x, bn = blockIdx.y;

    const uint32_t a_off = (uint32_t)(((l & 7) + ((l >> 3) & 1) * 8) * ROWB + (l >> 4) * 16);
    const uint32_t b_off = (uint32_t)(((l & 7) + (l >> 4) * 8) * ROWB + ((l >> 3) & 1) * 16);

    float acc[4][4][4];
#pragma unroll
    for (int mt = 0; mt < 4; mt++)
#pragma unroll
        for (int nt = 0; nt < 4; nt++)
#pragma unroll
            for (int i = 0; i < 4; i++) acc[mt][nt][i] = 0.0f;

    ld_stage_o(sb, A, W, bm, bn, 0, tid);
    ld_stage_o(sb, A, W, bm, bn, 1, tid);

#pragma unroll 1
    for (int kt = 0; kt < NKT; kt++) {
        if (kt < NKT - 2) asm volatile("cp.async.wait_group 1;" ::: "memory");
        else              asm volatile("cp.async.wait_group 0;" ::: "memory");
        __syncthreads();

        if (kt + 2 < NKT) ld_stage_o(sb, A, W, bm, bn, kt + 2, tid);

        const uint32_t As_u = sb + (uint32_t)((kt % GSTG) * OSTG_BYTES);
        const uint32_t Bs_u = As_u + OA_HALVES * 2;
        const uint32_t a_base = As_u + a_off;
        const uint32_t b_base = Bs_u + b_off + (uint32_t)(wn * 32 * ROWB);
#pragma unroll
        for (int ks = 0; ks < 4; ks++) {
            const uint32_t kb = ks * 32;
            uint32_t a[4][4], b[2][4];
#pragma unroll
            for (int mt = 0; mt < 4; mt++)
                ldsm_x4(a[mt], a_base + (uint32_t)(mt * 16 * ROWB) + kb);
            ldsm_x4(b[0], b_base + kb);
            ldsm_x4(b[1], b_base + (uint32_t)(16 * ROWB) + kb);
#pragma unroll
            for (int mt = 0; mt < 4; mt++)
#pragma unroll
                for (int nt = 0; nt < 4; nt++)
                    mma16(acc[mt][nt], a[mt], &b[nt >> 1][(nt & 1) * 2]);
        }
    }

    const int r_fr = l >> 2;
    const int c2 = (l & 3) * 2;
#pragma unroll
    for (int mt = 0; mt < 4; mt++) {
#pragma unroll
        for (int nt = 0; nt < 4; nt++) {
            int row = bm * OBM + mt * 16 + r_fr;
            int col = bn * GBN + wn * 32 + nt * 8 + c2;
            float b0 = bias[col], b1 = bias[col + 1];
            *reinterpret_cast<float2*>(&C[(size_t)row * 512 + col]) =
                make_float2(acc[mt][nt][0] + b0, acc[mt][nt][1] + b1);
            *reinterpret_cast<float2*>(&C[(size_t)(row + 8) * 512 + col]) =
                make_float2(acc[mt][nt][2] + b0, acc[mt][nt][3] + b1);
        }
    }
}

// ---------------- scanA: ek = exp(k), chunk partials of ek / ek*v ----------------
__global__ void scanA_kernel() {
    int ch = blockIdx.x * 256 + threadIdx.x;   // gridDim.x = 4
    int t0 = blockIdx.y * CHLEN;               // gridDim.y = 64
    float sn = 0.f, sd = 0.f;
#pragma unroll 4
    for (int i = 0; i < CHLEN; i++) {
        int t = t0 + i;
        float e = __expf(g_k[(size_t)t * NCH + ch]);
        g_ek[(size_t)t * NCH + ch] = e;
        sd += e;
        sn += e * g_v[(size_t)t * NCH + ch];
    }
    g_pden[ch * NCHUNK + blockIdx.y] = sd;     // [ch][chunk]
    g_pnum[ch * NCHUNK + blockIdx.y] = sn;
}

// ---------------- scanB: warp-per-channel exclusive prefix over 64 chunks ----------
__global__ void scanB_kernel() {
    const int ch   = (blockIdx.x << 3) + (threadIdx.x >> 5);   // 128 blocks x 8 warps
    const int lane = threadIdx.x & 31;
    float2* pn2 = reinterpret_cast<float2*>(g_pnum + ch * NCHUNK);
    float2* pd2 = reinterpret_cast<float2*>(g_pden + ch * NCHUNK);
    float2 an = pn2[lane];
    float2 ad = pd2[lane];
    float ln = an.x + an.y;
    float ld = ad.x + ad.y;
    float sn = ln, sd = ld;
#pragma unroll
    for (int off = 1; off < 32; off <<= 1) {
        float tn = __shfl_up_sync(0xffffffff, sn, off);
        float td = __shfl_up_sync(0xffffffff, sd, off);
        if (lane >= off) { sn += tn; sd += td; }
    }
    float en = sn - ln, ed = sd - ld;          // exclusive
    pn2[lane] = make_float2(en, en + an.x);
    pd2[lane] = make_float2(ed, ed + ad.x);
}

// ---------------- AFT: window + in-block prefix + gating -------------------------
// Block: 32 t-values x 64 channels. Halo rows t0-32 .. t0+31 (64 rows) in smem.
// num_out/den_out computed in-block: chunk-exclusive prefix + rows 0..tl of halo.
__global__ __launch_bounds__(256) void aft_kernel() {
    __shared__ float2 s_ek[64 * 32];
    __shared__ float2 s_v [64 * 32];
    __shared__ float  s_epb[32 * 32];

    const int tid = threadIdx.x;
    const int w = tid >> 5, l = tid & 31;
    const int bx = blockIdx.x;                 // 64 blocks
    const int t0 = bx << 5;
    const int chp = blockIdx.y * 32 + l;       // float2 channel index (0..511)

    const float2* ek2 = reinterpret_cast<const float2*>(g_ek);
    const float2* v2g = reinterpret_cast<const float2*>(g_v);

    for (int i = tid; i < 64 * 32; i += 256) {
        int r = i >> 5, cp = i & 31;
        int gr = t0 - 32 + r;
        float2 e = make_float2(0.f, 0.f), vv = make_float2(0.f, 0.f);
        if (gr >= 0) {
            size_t gi = (size_t)gr * 512 + blockIdx.y * 32 + cp;
            e  = ek2[gi];
            vv = v2g[gi];
        }
        s_ek[i] = e; s_v[i] = vv;
    }
    for (int i = tid; i < 1024; i += 256)
        s_epb[i] = g_epb[t0 * 32 + i];
    __syncthreads();

    const float2* q2g = reinterpret_cast<const float2*>(g_q);
    __half2* y2 = reinterpret_cast<__half2*>(g_hy);

    // running prefix starting at chunk-exclusive offset (zero for bx==0)
    float rn_x = 0.f, rn_y = 0.f, rd_x = 0.f, rd_y = 0.f;
    if (bx > 0) {
        int c0 = 2 * chp, c1 = 2 * chp + 1;
        rn_x = g_pnum[c0 * NCHUNK + bx - 1];
        rn_y = g_pnum[c1 * NCHUNK + bx - 1];
        rd_x = g_pden[c0 * NCHUNK + bx - 1];
        rd_y = g_pden[c1 * NCHUNK + bx - 1];
    }

    float acc[4][4];     // [ii][nx, ny, dx, dy]
    // rows 0..w  -> snapshot for ii=0 (tl = w)
    for (int r = 0; r <= w; r++) {
        float2 e2 = s_ek[(r << 5) + l];
        float2 vv = s_v [(r << 5) + l];
        rn_x += e2.x * vv.x; rn_y += e2.y * vv.y;
        rd_x += e2.x;        rd_y += e2.y;
    }
    acc[0][0] = rn_x; acc[0][1] = rn_y; acc[0][2] = rd_x; acc[0][3] = rd_y;
#pragma unroll
    for (int ii = 1; ii < 4; ii++) {
        int rbase = w + (ii - 1) * 8 + 1;
#pragma unroll
        for (int rr = 0; rr < 8; rr++) {
            int r = rbase + rr;
            float2 e2 = s_ek[(r << 5) + l];
            float2 vv = s_v [(r << 5) + l];
            rn_x += e2.x * vv.x; rn_y += e2.y * vv.y;
            rd_x += e2.x;        rd_y += e2.y;
        }
        acc[ii][0] = rn_x; acc[ii][1] = rn_y; acc[ii][2] = rd_x; acc[ii][3] = rd_y;
    }

    // window pass: rows r = w+1+s, s = 0..55; window ii contains s in [8ii, 8ii+31]
    const int ii_lo[7] = {0, 0, 0, 0, 1, 2, 3};
    const int ii_hi[7] = {0, 1, 2, 3, 3, 3, 3};
#pragma unroll
    for (int g = 0; g < 7; g++) {
#pragma unroll
        for (int rr = 0; rr < 8; rr++) {
            const int s = g * 8 + rr;
            const int row = w + 1 + s;         // 1..63
            float2 e2 = s_ek[(row << 5) + l];
            float2 vv = s_v [(row << 5) + l];
#pragma unroll
            for (int ii = ii_lo[g]; ii <= ii_hi[g]; ii++) {
                const int tl = w + (ii << 3);
                const int j  = s - (ii << 3);  // 0..31
                float ep = s_epb[(tl << 5) + j];   // warp-uniform broadcast
                float ex = e2.x * ep, ey = e2.y * ep;
                acc[ii][0] += ex * vv.x; acc[ii][1] += ey * vv.y;
                acc[ii][2] += ex;        acc[ii][3] += ey;
            }
        }
    }

#pragma unroll
    for (int ii = 0; ii < 4; ii++) {
        int t = t0 + w + (ii << 3);
        float2 q = q2g[(size_t)t * 512 + chp];
        float sx = 1.f / (1.f + __expf(-q.x));
        float sy = 1.f / (1.f + __expf(-q.y));
        y2[(size_t)t * 512 + chp] =
            __floats2half2_rn(sx * acc[ii][0] / acc[ii][2], sy * acc[ii][1] / acc[ii][3]);
    }
}

// ---------------- launch ----------------
extern "C" void kernel_launch(void* const* d_in, const int* in_sizes, int n_in,
                              void* d_out, int out_size) {
    const float* query = (const float*)d_in[0];
    const float* key   = (const float*)d_in[1];
    const float* value = (const float*)d_in[2];
    const float* Wq    = (const float*)d_in[3];
    const float* bq    = (const float*)d_in[4];
    const float* Wk    = (const float*)d_in[5];
    const float* bk    = (const float*)d_in[6];
    const float* Wv    = (const float*)d_in[7];
    const float* bv    = (const float*)d_in[8];
    const float* pb    = (const float*)d_in[9];
    const float* Wo    = (const float*)d_in[10];
    const float* bo    = (const float*)d_in[11];
    float* out = (float*)d_out;

    float *pq, *pk, *pv;
    __half *phx, *phw, *phy;
    cudaGetSymbolAddress((void**)&pq,  g_q);
    cudaGetSymbolAddress((void**)&pk,  g_k);
    cudaGetSymbolAddress((void**)&pv,  g_v);
    cudaGetSymbolAddress((void**)&phx, g_hx);
    cudaGetSymbolAddress((void**)&phw, g_hw);
    cudaGetSymbolAddress((void**)&phy, g_hy);

    cudaFuncSetAttribute(gemm_qkv, cudaFuncAttributeMaxDynamicSharedMemorySize, GEMM_SMEM);
    cudaFuncSetAttribute(gemm_o,   cudaFuncAttributeMaxDynamicSharedMemorySize, OGEMM_SMEM);

    // 1. fp16 rounding + epb table
    prep1_kernel<<<7424, 256>>>(pb, query, key, value, Wq, Wk, Wv, Wo);

    // 2. q/k/v projections
    dim3 ggrid3(M_ROWS / GBM, D_MODEL / GBN, 3);   // (32, 4, 3)
    gemm_qkv<<<ggrid3, 256, GEMM_SMEM>>>(phx, phw, bq, bk, bv, pq, pk, pv);

    // 3. ek + chunk partials, 4. exclusive chunk prefix
    scanA_kernel<<<dim3(4, NCHUNK), 256>>>();
    scanB_kernel<<<128, 256>>>();

    // 5. AFT window + in-block prefix + gating (writes fp16 y)
    aft_kernel<<<dim3(64, 16), 256>>>();

    // 6. output projection
    dim3 ogrid(M_ROWS / OBM, D_MODEL / GBN);       // (64, 4)
    gemm_o<<<ogrid, 128, OGEMM_SMEM>>>(phy, phw + 3 * D_MODEL * D_MODEL, bo, out);
}